// round 11
// baseline (speedup 1.0000x reference)
#include <cuda_runtime.h>
#include <math.h>

#define BB 16
#define LL 2048
#define HH 256
#define NS 64
#define NLAYER 4
#define FIN 75
#define G2 512
#define REPR 512
#define TCH 128      // chunk length
#define NCHUNK 16    // LL/TCH
#define JCOLS 256    // NCHUNK*BB
#define EK 80

// ---- device scratch ----
__device__ float g_hT[BB*LL*HH];     // residual stream, token-major (fp32)
__device__ float g_ucm[BB*HH*LL];    // LN output, channel-major (tf32-rounded)
__device__ float g_ycm[BB*HH*LL];    // scan output (tf32-rounded)
__device__ float g_xp[(size_t)BB*LL*EK];  // padded+rounded x
__device__ float g_wr[NLAYER*HH*NS];
__device__ float g_wi[NLAYER*HH*NS];
__device__ float g_cr[NLAYER*HH*NS];
__device__ float g_ci[NLAYER*HH*NS];
__device__ float g_P[(size_t)NLAYER*HH*TCH*128];      // tf32-rounded
__device__ float g_AC[(size_t)NLAYER*HH*256*TCH];     // tf32-rounded
__device__ float g_F[(size_t)HH*JCOLS*128];           // fp32 (scan input)
__device__ float g_S[(size_t)HH*JCOLS*128];           // tf32-rounded
__device__ float g_Wt[(size_t)NLAYER*G2*HH];          // out_W tf32-rounded
__device__ float g_wTr[NLAYER*HH*NS];
__device__ float g_wTi[NLAYER*HH*NS];

__device__ __forceinline__ unsigned cvt_tf32(float f) {
    unsigned r;
    asm("cvt.rna.tf32.f32 %0, %1;" : "=r"(r) : "f"(f));
    return r;
}
__device__ __forceinline__ float round_tf32(float f) { return __uint_as_float(cvt_tf32(f)); }

__device__ __forceinline__ void mma_tf32(float c[4], const unsigned a[4], unsigned b0, unsigned b1) {
    asm volatile("mma.sync.aligned.m16n8k8.row.col.f32.tf32.tf32.f32 "
                 "{%0,%1,%2,%3}, {%4,%5,%6,%7}, {%8,%9}, {%0,%1,%2,%3};"
                 : "+f"(c[0]), "+f"(c[1]), "+f"(c[2]), "+f"(c[3])
                 : "r"(a[0]), "r"(a[1]), "r"(a[2]), "r"(a[3]), "r"(b0), "r"(b1));
}

__device__ __forceinline__ void cp_async16(float* smem_dst, const float* gmem_src) {
    unsigned s = (unsigned)__cvta_generic_to_shared(smem_dst);
    asm volatile("cp.async.ca.shared.global [%0], [%1], 16;" :: "r"(s), "l"(gmem_src));
}
#define CP_COMMIT() asm volatile("cp.async.commit_group;")
#define CP_WAIT1()  asm volatile("cp.async.wait_group 1;")
#define CP_WAIT0()  asm volatile("cp.async.wait_group 0;")

__device__ __forceinline__ void st_tf32_4(float* dst, float4 v) {
    unsigned* d = (unsigned*)dst;
    d[0] = cvt_tf32(v.x); d[1] = cvt_tf32(v.y);
    d[2] = cvt_tf32(v.z); d[3] = cvt_tf32(v.w);
}

__device__ __forceinline__ float gelu_f(float v) {
    float x3 = v*v*v;
    return 0.5f*v*(1.0f + tanhf(fmaf(0.0356774081f, x3, 0.7978845608f*v)));
}

// ---------------------------------------------------------------------------
__global__ void precompute_kernel(const float* __restrict__ log_dt,
                                  const float* __restrict__ A_log_re,
                                  const float* __restrict__ A_im,
                                  const float* __restrict__ C_re,
                                  const float* __restrict__ C_im) {
    int idx = blockIdx.x * blockDim.x + threadIdx.x;
    if (idx >= NLAYER*HH*NS) return;
    int i = idx / (HH*NS);
    int h = (idx / NS) % HH;
    float dt  = expf(log_dt[i*HH + h]);
    float Are = -expf(A_log_re[idx]);
    float Aim = A_im[idx];
    float er = dt*Are, ei = dt*Aim;
    float mag = expf(er);
    float wr = mag*cosf(ei), wi = mag*sinf(ei);
    float nr = wr - 1.0f, ni = wi;
    float den = Are*Are + Aim*Aim;
    float inv = 1.0f/den;
    float qr = (nr*Are + ni*Aim)*inv;
    float qi = (ni*Are - nr*Aim)*inv;
    float cr = C_re[idx], ci = C_im[idx];
    g_wr[idx] = wr; g_wi[idx] = wi;
    g_cr[idx] = 2.0f*(cr*qr - ci*qi);
    g_ci[idx] = 2.0f*(cr*qi + ci*qr);
}

// ---------------------------------------------------------------------------
__global__ void roundW_kernel(const float* __restrict__ W) {
    int i = blockIdx.x*256 + threadIdx.x;
    g_Wt[i] = round_tf32(W[i]);
}

// ---------------------------------------------------------------------------
// Pad + round x: (B*L,75) -> g_xp (B*L,80), tf32-rounded, zero-padded.
// ---------------------------------------------------------------------------
__global__ void pad_x_kernel(const float* __restrict__ x) {
    int r0 = blockIdx.x * 8;
    for (int i = threadIdx.x; i < 8*EK; i += 256) {
        int rr = i / EK, k = i % EK;
        int row = r0 + rr;
        float v = (k < FIN) ? round_tf32(x[(size_t)row*FIN + k]) : 0.f;
        g_xp[(size_t)row*EK + k] = v;
    }
}

// ---------------------------------------------------------------------------
// Precompute P, AC, w^T per (layer,h). P/AC stored tf32-rounded.
// ---------------------------------------------------------------------------
__global__ void precompute2_kernel() {
    extern __shared__ float ps[];
    float* wpr = ps;
    float* wpi = ps + 129*68;
    float* sK  = wpi + 129*68;
    int tid = threadIdx.x;
    int lh = blockIdx.x;
    int ib = lh*NS;
    if (tid < 64) {
        int n = tid;
        float wr = g_wr[ib+n], wi = g_wi[ib+n];
        float pr = 1.f, pi = 0.f;
        for (int d = 0; d <= 128; d++) {
            wpr[d*68+n] = pr; wpi[d*68+n] = pi;
            float nr = pr*wr - pi*wi;
            float ni = pr*wi + pi*wr;
            pr = nr; pi = ni;
        }
    }
    __syncthreads();
    {
        int d = tid;
        float s = 0.f;
        for (int n = 0; n < 64; n++)
            s += g_cr[ib+n]*wpr[d*68+n] - g_ci[ib+n]*wpi[d*68+n];
        sK[d] = s;
    }
    if (tid < 64) {
        g_wTr[ib+tid] = wpr[128*68+tid];
        g_wTi[ib+tid] = wpi[128*68+tid];
    }
    __syncthreads();
    size_t pbase = (size_t)lh*TCH*128;
    int n2 = tid;
    for (int tau = 0; tau < TCH; tau++) {
        float v = (n2 < 64) ? wpr[(127-tau)*68 + n2] : wpi[(127-tau)*68 + (n2-64)];
        g_P[pbase + (size_t)tau*128 + n2] = round_tf32(v);
    }
    size_t acbase = (size_t)lh*256*TCH;
    int t = tid;
    for (int tau = 0; tau < TCH; tau++)
        g_AC[acbase + (size_t)tau*TCH + t] = (t >= tau) ? round_tf32(sK[t - tau]) : 0.f;
    for (int q2 = 0; q2 < 128; q2++) {
        int n = q2 & 63;
        float cr = g_cr[ib+n], ci = g_ci[ib+n];
        float wr = wpr[(t+1)*68 + n], wi = wpi[(t+1)*68 + n];
        float v = (q2 < 64) ? (cr*wr - ci*wi) : -(cr*wi + ci*wr);
        g_AC[acbase + (size_t)(128 + q2)*TCH + t] = round_tf32(v);
    }
}

// ---------------------------------------------------------------------------
// Embed as tf32 GEMM: g_xp(B*L,80)@(75,256)+b -> g_hT.
// Block tile 128(m) x 64(n), 256 threads = 8 warps (4m x 2n), warp 32x32.
// A staged via cp.async from padded g_xp.
// ---------------------------------------------------------------------------
__global__ void __launch_bounds__(256) embed_tc_kernel(const float* __restrict__ W,
                                                       const float* __restrict__ bias) {
    extern __shared__ float sm[];
    float* As = sm;              // [128][84]
    float* Bs = sm + 128*84;     // [80][72]
    int tid = threadIdx.x;
    int warp = tid >> 5, lane = tid & 31;
    int wm = warp & 3, wn = warp >> 2;
    int gid = lane >> 2, tig = lane & 3;
    int n0 = blockIdx.x * 64;
    int m0 = blockIdx.y * 128;

    // Stage A: 128 rows x 80 k via cp.async (g_xp stride 320B, 16B-aligned)
    #pragma unroll
    for (int i = 0; i < 10; i++) {
        int idx = tid + i*256;           // 0..2559 f4s
        int row = idx / 20, kq = idx % 20;
        cp_async16(&As[row*84 + kq*4], &g_xp[(size_t)(m0 + row)*EK + kq*4]);
    }
    CP_COMMIT();
    // Stage B: 80 k-rows x 64 n (W [75][256] row-major, small & L2-hot)
    for (int i = tid; i < EK*64; i += 256) {
        int k = i >> 6, n = i & 63;
        float v = (k < FIN) ? W[k*HH + n0 + n] : 0.f;
        Bs[k*72 + n] = __uint_as_float(cvt_tf32(v));
    }
    CP_WAIT0();
    __syncthreads();

    float acc[2][4][4];
    #pragma unroll
    for (int i = 0; i < 2; i++)
        #pragma unroll
        for (int j = 0; j < 4; j++)
            #pragma unroll
            for (int q = 0; q < 4; q++) acc[i][j][q] = 0.f;

    #pragma unroll
    for (int k8 = 0; k8 < EK; k8 += 8) {
        unsigned a[2][4];
        #pragma unroll
        for (int m2 = 0; m2 < 2; m2++) {
            int l = wm*32 + m2*16 + gid;
            a[m2][0] = __float_as_uint(As[l*84 + k8 + tig]);
            a[m2][1] = __float_as_uint(As[(l + 8)*84 + k8 + tig]);
            a[m2][2] = __float_as_uint(As[l*84 + k8 + 4 + tig]);
            a[m2][3] = __float_as_uint(As[(l + 8)*84 + k8 + 4 + tig]);
        }
        #pragma unroll
        for (int nt = 0; nt < 4; nt++) {
            int n = wn*32 + nt*8 + gid;
            unsigned b0 = __float_as_uint(Bs[(k8 + tig)*72 + n]);
            unsigned b1 = __float_as_uint(Bs[(k8 + 4 + tig)*72 + n]);
            #pragma unroll
            for (int m2 = 0; m2 < 2; m2++)
                mma_tf32(acc[m2][nt], a[m2], b0, b1);
        }
    }
    #pragma unroll
    for (int m2 = 0; m2 < 2; m2++) {
        #pragma unroll
        for (int nt = 0; nt < 4; nt++) {
            #pragma unroll
            for (int q = 0; q < 4; q++) {
                int row = m0 + wm*32 + m2*16 + gid + ((q >> 1) ? 8 : 0);
                int col = n0 + wn*32 + nt*8 + 2*tig + (q & 1);
                g_hT[(size_t)row*HH + col] = acc[m2][nt][q] + bias[col];
            }
        }
    }
}

// ---------------------------------------------------------------------------
// LayerNorm + transpose; output tf32-rounded (GEMM operand).
// ---------------------------------------------------------------------------
__global__ void ln_kernel(const float* __restrict__ gvec,
                          const float* __restrict__ bvec) {
    __shared__ float s[32][HH+1];
    __shared__ float sg[HH], sb[HH];
    int tid = threadIdx.x;
    sg[tid] = gvec[tid]; sb[tid] = bvec[tid];
    int blk = blockIdx.x;
    int b = blk / (LL/32);
    int l0 = (blk % (LL/32)) * 32;
    int warp = tid >> 5, lane = tid & 31;
    __syncthreads();
    for (int tt = 0; tt < 4; tt++) {
        int t = warp*4 + tt;
        const float* p = g_hT + ((size_t)(b*LL + l0 + t))*HH;
        float v[8];
        float sum = 0.f;
        #pragma unroll
        for (int j = 0; j < 8; j++) { v[j] = p[lane + 32*j]; sum += v[j]; }
        #pragma unroll
        for (int o = 16; o; o >>= 1) sum += __shfl_xor_sync(0xffffffffu, sum, o);
        float mean = sum * (1.0f/HH);
        float var = 0.f;
        #pragma unroll
        for (int j = 0; j < 8; j++) { float d = v[j]-mean; var = fmaf(d, d, var); }
        #pragma unroll
        for (int o = 16; o; o >>= 1) var += __shfl_xor_sync(0xffffffffu, var, o);
        float rstd = rsqrtf(var*(1.0f/HH) + 1e-5f);
        #pragma unroll
        for (int j = 0; j < 8; j++) {
            int c = lane + 32*j;
            s[t][c] = (v[j]-mean)*rstd*sg[c] + sb[c];
        }
    }
    __syncthreads();
    #pragma unroll 4
    for (int it = 0; it < 32; it++) {
        int h = it*8 + (tid >> 5);
        int ll = tid & 31;
        g_ucm[((size_t)(b*HH + h))*LL + l0 + ll] = round_tf32(s[ll][h]);
    }
}

// ---------------------------------------------------------------------------
// GEMM-F (cp.async 2-stage, 256 thr, warp 32mx64n): F = U @ P  M=128 N=128 K=128
// ---------------------------------------------------------------------------
__global__ void __launch_bounds__(256) gemm_f_kernel(int layer) {
    extern __shared__ float sm[];
    float* AsB[2] = { sm,            sm + 128*36 };
    float* BsB[2] = { sm + 2*128*36, sm + 2*128*36 + 32*136 };
    int tid = threadIdx.x;
    int warp = tid >> 5, lane = tid & 31;
    int wm = warp & 3, wn = warp >> 2;     // wn 0..1
    int gid = lane >> 2, tig = lane & 3;
    int h = blockIdx.y;
    int j0 = blockIdx.x * 128;
    const float* P = g_P + (size_t)(layer*HH + h)*TCH*128;

    int ar[4], akq[4], bk[4], bq[4];
    size_t ab[4];
    #pragma unroll
    for (int i = 0; i < 4; i++) {
        int idx = tid + i*256;
        ar[i] = idx >> 3; akq[i] = idx & 7;
        int jA = j0 + ar[i];
        ab[i] = ((size_t)((jA & 15)*HH + h))*LL + (jA >> 4)*TCH + akq[i]*4;
        bk[i] = idx >> 5; bq[i] = idx & 31;
    }

    float acc[2][8][4];
    #pragma unroll
    for (int i = 0; i < 2; i++)
        #pragma unroll
        for (int j = 0; j < 8; j++)
            #pragma unroll
            for (int q = 0; q < 4; q++) acc[i][j][q] = 0.f;

#define GF_ISSUE(k0, buf) { \
    _Pragma("unroll") \
    for (int i = 0; i < 4; i++) \
        cp_async16(&AsB[buf][ar[i]*36 + akq[i]*4], &g_ucm[ab[i] + (k0)]); \
    _Pragma("unroll") \
    for (int i = 0; i < 4; i++) \
        cp_async16(&BsB[buf][bk[i]*136 + bq[i]*4], &P[(size_t)((k0) + bk[i])*128 + bq[i]*4]); \
    CP_COMMIT(); }

    GF_ISSUE(0, 0);
    for (int c = 0; c < 4; c++) {
        if (c < 3) { GF_ISSUE((c+1)*32, (c+1)&1); CP_WAIT1(); } else { CP_WAIT0(); }
        __syncthreads();
        float* As = AsB[c & 1];
        float* Bs = BsB[c & 1];
        #pragma unroll
        for (int k8 = 0; k8 < 32; k8 += 8) {
            unsigned a[2][4];
            #pragma unroll
            for (int m2 = 0; m2 < 2; m2++) {
                int l = wm*32 + m2*16 + gid;
                a[m2][0] = __float_as_uint(As[l*36 + k8 + tig]);
                a[m2][1] = __float_as_uint(As[(l + 8)*36 + k8 + tig]);
                a[m2][2] = __float_as_uint(As[l*36 + k8 + 4 + tig]);
                a[m2][3] = __float_as_uint(As[(l + 8)*36 + k8 + 4 + tig]);
            }
            #pragma unroll
            for (int nt = 0; nt < 8; nt++) {
                int n = wn*64 + nt*8 + gid;
                unsigned b0 = __float_as_uint(Bs[(k8 + tig)*136 + n]);
                unsigned b1 = __float_as_uint(Bs[(k8 + 4 + tig)*136 + n]);
                #pragma unroll
                for (int m2 = 0; m2 < 2; m2++)
                    mma_tf32(acc[m2][nt], a[m2], b0, b1);
            }
        }
        __syncthreads();
    }
    #pragma unroll
    for (int m2 = 0; m2 < 2; m2++) {
        #pragma unroll
        for (int nt = 0; nt < 8; nt++) {
            #pragma unroll
            for (int q = 0; q < 4; q++) {
                int row = wm*32 + m2*16 + gid + ((q >> 1) ? 8 : 0);
                int col = wn*64 + nt*8 + 2*tig + (q & 1);
                g_F[((size_t)h*JCOLS + j0 + row)*128 + col] = acc[m2][nt][q];
            }
        }
    }
}

// ---------------------------------------------------------------------------
__global__ void chunkscan_kernel(int layer) {
    int g = blockIdx.x*256 + threadIdx.x;
    int h = g >> 10;
    int r = g & 1023;
    int bb = r >> 6;
    int n = r & 63;
    int ib = (layer*HH + h)*NS + n;
    float wtr = g_wTr[ib], wti = g_wTi[ib];
    float sre = 0.f, sim = 0.f;
    size_t base = (size_t)h*JCOLS*128;
    #pragma unroll
    for (int c = 0; c < NCHUNK; c++) {
        size_t jo = base + (size_t)(c*16 + bb)*128;
        g_S[jo + n]      = round_tf32(sre);
        g_S[jo + 64 + n] = round_tf32(sim);
        float fre = g_F[jo + n];
        float fim = g_F[jo + 64 + n];
        float nr = fmaf(wtr, sre, fmaf(-wti, sim, fre));
        float ni = fmaf(wtr, sim, fmaf(wti, sre, fim));
        sre = nr; sim = ni;
    }
}

// ---------------------------------------------------------------------------
// GEMM-Y (cp.async 2-stage, 256 thr, warp 32mx64n): y = [U|S] @ AC  M=128 N=128 K=256
// ---------------------------------------------------------------------------
__global__ void __launch_bounds__(256) gemm_y_kernel(int layer, const float* __restrict__ Dski) {
    extern __shared__ float sm[];
    float* AsB[2] = { sm,            sm + 128*36 };
    float* BsB[2] = { sm + 2*128*36, sm + 2*128*36 + 32*136 };
    int tid = threadIdx.x;
    int warp = tid >> 5, lane = tid & 31;
    int wm = warp & 3, wn = warp >> 2;
    int gid = lane >> 2, tig = lane & 3;
    int h = blockIdx.y;
    int j0 = blockIdx.x * 128;
    const float* AC = g_AC + (size_t)(layer*HH + h)*256*TCH;

    int ar[4], akq[4], bk[4], bq[4];
    size_t aub[4], asb[4];
    #pragma unroll
    for (int i = 0; i < 4; i++) {
        int idx = tid + i*256;
        ar[i] = idx >> 3; akq[i] = idx & 7;
        int jA = j0 + ar[i];
        aub[i] = ((size_t)((jA & 15)*HH + h))*LL + (jA >> 4)*TCH + akq[i]*4;
        asb[i] = ((size_t)h*JCOLS + jA)*128 + akq[i]*4;
        bk[i] = idx >> 5; bq[i] = idx & 31;
    }

    float acc[2][8][4];
    #pragma unroll
    for (int i = 0; i < 2; i++)
        #pragma unroll
        for (int j = 0; j < 8; j++)
            #pragma unroll
            for (int q = 0; q < 4; q++) acc[i][j][q] = 0.f;

#define GY_ISSUE(k0, buf) { \
    _Pragma("unroll") \
    for (int i = 0; i < 4; i++) { \
        const float* src = ((k0) < TCH) ? &g_ucm[aub[i] + (k0)] : &g_S[asb[i] + (k0) - TCH]; \
        cp_async16(&AsB[buf][ar[i]*36 + akq[i]*4], src); } \
    _Pragma("unroll") \
    for (int i = 0; i < 4; i++) \
        cp_async16(&BsB[buf][bk[i]*136 + bq[i]*4], &AC[(size_t)((k0) + bk[i])*TCH + bq[i]*4]); \
    CP_COMMIT(); }

    GY_ISSUE(0, 0);
    for (int c = 0; c < 8; c++) {
        if (c < 7) { GY_ISSUE((c+1)*32, (c+1)&1); CP_WAIT1(); } else { CP_WAIT0(); }
        __syncthreads();
        float* As = AsB[c & 1];
        float* Bs = BsB[c & 1];
        #pragma unroll
        for (int k8 = 0; k8 < 32; k8 += 8) {
            unsigned a[2][4];
            #pragma unroll
            for (int m2 = 0; m2 < 2; m2++) {
                int l = wm*32 + m2*16 + gid;
                a[m2][0] = __float_as_uint(As[l*36 + k8 + tig]);
                a[m2][1] = __float_as_uint(As[(l + 8)*36 + k8 + tig]);
                a[m2][2] = __float_as_uint(As[l*36 + k8 + 4 + tig]);
                a[m2][3] = __float_as_uint(As[(l + 8)*36 + k8 + 4 + tig]);
            }
            #pragma unroll
            for (int nt = 0; nt < 8; nt++) {
                int n = wn*64 + nt*8 + gid;
                unsigned b0 = __float_as_uint(Bs[(k8 + tig)*136 + n]);
                unsigned b1 = __float_as_uint(Bs[(k8 + 4 + tig)*136 + n]);
                #pragma unroll
                for (int m2 = 0; m2 < 2; m2++)
                    mma_tf32(acc[m2][nt], a[m2], b0, b1);
            }
        }
        __syncthreads();
    }
    float D = Dski[h];
    #pragma unroll
    for (int m2 = 0; m2 < 2; m2++) {
        #pragma unroll
        for (int nt = 0; nt < 8; nt++) {
            #pragma unroll
            for (int q = 0; q < 4; q++) {
                int row = wm*32 + m2*16 + gid + ((q >> 1) ? 8 : 0);
                int j = j0 + row;
                int t = wn*64 + nt*8 + 2*tig + (q & 1);
                int c = j >> 4, bb = j & 15;
                size_t base = ((size_t)(bb*HH + h))*LL + c*TCH;
                float u = g_ucm[base + t];
                float yv = fmaf(D, u, acc[m2][nt][q]);
                g_ycm[base + t] = round_tf32(gelu_f(yv));
            }
        }
    }
}

// ---------------------------------------------------------------------------
// GLU out-projection + residual (cp.async 2-stage) — unchanged from R10.
// ---------------------------------------------------------------------------
__global__ void __launch_bounds__(256) glu_tc_kernel(int layer, const float* __restrict__ bias) {
    extern __shared__ float sm[];
    float* AsB[2]  = { sm,             sm + 32*136 };
    float* Bs1B[2] = { sm + 2*32*136,  sm + 2*32*136 + 64*36 };
    float* Bs2B[2] = { sm + 2*32*136 + 2*64*36, sm + 2*32*136 + 3*64*36 };
    const float* W = g_Wt + (size_t)layer*G2*HH;
    int tid = threadIdx.x;
    int warp = tid >> 5, lane = tid & 31;
    int wm = warp & 3, wn = warp >> 2;
    int gid = lane >> 2, tig = lane & 3;
    int g0 = blockIdx.x * 64;
    int mt = blockIdx.y;
    int b  = mt >> 4;
    int l0 = (mt & 15) * 128;

    int a_kk[4], a_lq[4];
    #pragma unroll
    for (int i = 0; i < 4; i++) { int f4 = tid + i*256; a_kk[i] = f4 >> 5; a_lq[i] = f4 & 31; }
    int bg[2], bkk[2];
    #pragma unroll
    for (int i = 0; i < 2; i++) { int f4 = tid + i*256; bg[i] = f4 >> 3; bkk[i] = f4 & 7; }

    float acc1[2][4][4], acc2[2][4][4];
    #pragma unroll
    for (int i = 0; i < 2; i++)
        #pragma unroll
        for (int j = 0; j < 4; j++)
            #pragma unroll
            for (int q = 0; q < 4; q++) { acc1[i][j][q] = 0.f; acc2[i][j][q] = 0.f; }

#define GL_ISSUE(k0, buf) { \
    _Pragma("unroll") \
    for (int i = 0; i < 4; i++) \
        cp_async16(&AsB[buf][a_kk[i]*136 + a_lq[i]*4], \
                   &g_ycm[((size_t)(b*HH + (k0) + a_kk[i]))*LL + l0 + a_lq[i]*4]); \
    _Pragma("unroll") \
    for (int i = 0; i < 2; i++) { \
        cp_async16(&Bs1B[buf][bg[i]*36 + bkk[i]*4], &W[(size_t)(g0 + bg[i])*HH + (k0) + bkk[i]*4]); \
        cp_async16(&Bs2B[buf][bg[i]*36 + bkk[i]*4], &W[(size_t)(g0 + 256 + bg[i])*HH + (k0) + bkk[i]*4]); } \
    CP_COMMIT(); }

    GL_ISSUE(0, 0);
    for (int c = 0; c < 8; c++) {
        if (c < 7) { GL_ISSUE((c+1)*32, (c+1)&1); CP_WAIT1(); } else { CP_WAIT0(); }
        __syncthreads();
        float* As  = AsB[c & 1];
        float* Bs1 = Bs1B[c & 1];
        float* Bs2 = Bs2B[c & 1];
        #pragma unroll
        for (int k8 = 0; k8 < 32; k8 += 8) {
            unsigned a[2][4];
            #pragma unroll
            for (int m2 = 0; m2 < 2; m2++) {
                int l = wm*32 + m2*16 + gid;
                a[m2][0] = __float_as_uint(As[(k8 + tig)*136 + l]);
                a[m2][1] = __float_as_uint(As[(k8 + tig)*136 + l + 8]);
                a[m2][2] = __float_as_uint(As[(k8 + 4 + tig)*136 + l]);
                a[m2][3] = __float_as_uint(As[(k8 + 4 + tig)*136 + l + 8]);
            }
            #pragma unroll
            for (int nt = 0; nt < 4; nt++) {
                int n = wn*32 + nt*8 + gid;
                unsigned b10 = __float_as_uint(Bs1[n*36 + k8 + tig]);
                unsigned b11 = __float_as_uint(Bs1[n*36 + k8 + 4 + tig]);
                unsigned b20 = __float_as_uint(Bs2[n*36 + k8 + tig]);
                unsigned b21 = __float_as_uint(Bs2[n*36 + k8 + 4 + tig]);
                #pragma unroll
                for (int m2 = 0; m2 < 2; m2++) {
                    mma_tf32(acc1[m2][nt], a[m2], b10, b11);
                    mma_tf32(acc2[m2][nt], a[m2], b20, b21);
                }
            }
        }
        __syncthreads();
    }
    #pragma unroll
    for (int m2 = 0; m2 < 2; m2++) {
        #pragma unroll
        for (int nt = 0; nt < 4; nt++) {
            #pragma unroll
            for (int q = 0; q < 4; q++) {
                int row = l0 + wm*32 + m2*16 + gid + ((q >> 1) ? 8 : 0);
                int col = g0 + wn*32 + nt*8 + 2*tig + (q & 1);
                float z1 = acc1[m2][nt][q] + bias[col];
                float z2 = acc2[m2][nt][q] + bias[col + 256];
                float sig = 1.0f/(1.0f + expf(-z2));
                g_hT[((size_t)(b*LL + row))*HH + col] += z1*sig;
            }
        }
    }
}

// ---------------------------------------------------------------------------
// Decoder (synchronous): (B*L,256)@(256,512)+b -> out — unchanged from R10.
// ---------------------------------------------------------------------------
__global__ void __launch_bounds__(256) dec_tc_kernel(const float* __restrict__ W,
                                                     const float* __restrict__ bias,
                                                     float* __restrict__ out) {
    __shared__ float As[128*36];
    __shared__ float Bs[32*72];
    int tid = threadIdx.x;
    int warp = tid >> 5, lane = tid & 31;
    int wm = warp & 3, wn = warp >> 2;
    int gid = lane >> 2, tig = lane & 3;
    int r0 = blockIdx.x * 64;
    int m0 = blockIdx.y * 128;

    float acc[2][4][4];
    #pragma unroll
    for (int i = 0; i < 2; i++)
        #pragma unroll
        for (int j = 0; j < 4; j++)
            #pragma unroll
            for (int q = 0; q < 4; q++) acc[i][j][q] = 0.f;

    for (int k0 = 0; k0 < HH; k0 += 32) {
        #pragma unroll
        for (int i = 0; i < 4; i++) {
            int f4 = tid + i*256;
            int l = f4 >> 3, kq = f4 & 7;
            float4 v = *(const float4*)&g_hT[((size_t)(m0 + l))*HH + k0 + kq*4];
            st_tf32_4(&As[l*36 + kq*4], v);
        }
        #pragma unroll
        for (int i = 0; i < 2; i++) {
            int f4 = tid + i*256;
            int kk = f4 >> 4, rq = f4 & 15;
            float4 v = *(const float4*)&W[(size_t)(k0 + kk)*REPR + r0 + rq*4];
            st_tf32_4(&Bs[kk*72 + rq*4], v);
        }
        __syncthreads();
        #pragma unroll
        for (int k8 = 0; k8 < 32; k8 += 8) {
            unsigned a[2][4];
            #pragma unroll
            for (int m2 = 0; m2 < 2; m2++) {
                int l = wm*32 + m2*16 + gid;
                a[m2][0] = __float_as_uint(As[l*36 + k8 + tig]);
                a[m2][1] = __float_as_uint(As[(l + 8)*36 + k8 + tig]);
                a[m2][2] = __float_as_uint(As[l*36 + k8 + 4 + tig]);
                a[m2][3] = __float_as_uint(As[(l + 8)*36 + k8 + 4 + tig]);
            }
            #pragma unroll
            for (int nt = 0; nt < 4; nt++) {
                int n = wn*32 + nt*8 + gid;
                unsigned b0 = __float_as_uint(Bs[(k8 + tig)*72 + n]);
                unsigned b1 = __float_as_uint(Bs[(k8 + 4 + tig)*72 + n]);
                #pragma unroll
                for (int m2 = 0; m2 < 2; m2++)
                    mma_tf32(acc[m2][nt], a[m2], b0, b1);
            }
        }
        __syncthreads();
    }
    #pragma unroll
    for (int m2 = 0; m2 < 2; m2++) {
        #pragma unroll
        for (int nt = 0; nt < 4; nt++) {
            #pragma unroll
            for (int q = 0; q < 4; q++) {
                int row = m0 + wm*32 + m2*16 + gid + ((q >> 1) ? 8 : 0);
                int col = r0 + wn*32 + nt*8 + 2*tig + (q & 1);
                out[(size_t)row*REPR + col] = acc[m2][nt][q] + bias[col];
            }
        }
    }
}

// ---------------------------------------------------------------------------
extern "C" void kernel_launch(void* const* d_in, const int* in_sizes, int n_in,
                              void* d_out, int out_size) {
    const float* x        = (const float*)d_in[0];
    const float* embed_W  = (const float*)d_in[1];
    const float* embed_b  = (const float*)d_in[2];
    const float* log_dt   = (const float*)d_in[3];
    const float* A_log_re = (const float*)d_in[4];
    const float* A_im     = (const float*)d_in[5];
    const float* C_re     = (const float*)d_in[6];
    const float* C_im     = (const float*)d_in[7];
    const float* D_skip   = (const float*)d_in[8];
    const float* out_W    = (const float*)d_in[9];
    const float* out_b    = (const float*)d_in[10];
    const float* ln_g     = (const float*)d_in[11];
    const float* ln_b     = (const float*)d_in[12];
    const float* dec_W    = (const float*)d_in[13];
    const float* dec_b    = (const float*)d_in[14];
    float* out = (float*)d_out;

    const int PRE2_SMEM = (2*129*68 + 128) * sizeof(float);
    const int EMB_SMEM = (128*84 + EK*72) * sizeof(float);        // 66048
    const int GF_SMEM  = (2*128*36 + 2*32*136) * sizeof(float);   // 71680
    const int GY_SMEM  = GF_SMEM;
    const int GL_SMEM  = (2*32*136 + 4*64*36) * sizeof(float);    // 71680
    static int smem_set = 0;
    if (!smem_set) {
        cudaFuncSetAttribute(embed_tc_kernel, cudaFuncAttributeMaxDynamicSharedMemorySize, EMB_SMEM);
        cudaFuncSetAttribute(precompute2_kernel, cudaFuncAttributeMaxDynamicSharedMemorySize,
                             PRE2_SMEM);
        cudaFuncSetAttribute(gemm_f_kernel, cudaFuncAttributeMaxDynamicSharedMemorySize, GF_SMEM);
        cudaFuncSetAttribute(gemm_y_kernel, cudaFuncAttributeMaxDynamicSharedMemorySize, GY_SMEM);
        cudaFuncSetAttribute(glu_tc_kernel, cudaFuncAttributeMaxDynamicSharedMemorySize, GL_SMEM);
        smem_set = 1;
    }

    precompute_kernel<<<(NLAYER*HH*NS + 255)/256, 256>>>(log_dt, A_log_re, A_im, C_re, C_im);
    precompute2_kernel<<<NLAYER*HH, 128, PRE2_SMEM>>>();
    roundW_kernel<<<NLAYER*G2*HH/256, 256>>>(out_W);
    pad_x_kernel<<<BB*LL/8, 256>>>(x);
    embed_tc_kernel<<<dim3(4, BB*LL/128), 256, EMB_SMEM>>>(embed_W, embed_b);
    for (int i = 0; i < NLAYER; i++) {
        ln_kernel<<<BB*LL/32, 256>>>(ln_g + i*HH, ln_b + i*HH);
        gemm_f_kernel<<<dim3(2, HH), 256, GF_SMEM>>>(i);
        chunkscan_kernel<<<HH*BB*NS/256, 256>>>(i);
        gemm_y_kernel<<<dim3(2, HH), 256, GY_SMEM>>>(i, D_skip + i*HH);
        glu_tc_kernel<<<dim3(4, BB*LL/128), 256, GL_SMEM>>>(i, out_b + i*G2);
    }
    dec_tc_kernel<<<dim3(REPR/64, BB*LL/128), 256>>>(dec_W, dec_b, out);
}

// round 14
// speedup vs baseline: 1.0556x; 1.0556x over previous
#include <cuda_runtime.h>
#include <cuda_fp16.h>
#include <stdint.h>
#include <math.h>

#define BB 16
#define LL 2048
#define HH 256
#define NS 64
#define NLAYER 4
#define FIN 75
#define G2 512
#define REPR 512
#define TCH 128      // chunk length
#define NCHUNK 16    // LL/TCH
#define JCOLS 256    // NCHUNK*BB

// ---- device scratch ----
__device__ float g_hT[BB*LL*HH];     // residual stream, token-major (fp32)
__device__ float g_ucm[BB*HH*LL];    // LN output, channel-major (tf32-rounded)
__device__ float g_ycm[BB*HH*LL];    // scan output (tf32-rounded)
__device__ float g_wr[NLAYER*HH*NS];
__device__ float g_wi[NLAYER*HH*NS];
__device__ float g_cr[NLAYER*HH*NS];
__device__ float g_ci[NLAYER*HH*NS];
__device__ float g_P[(size_t)NLAYER*HH*TCH*128];      // tf32-rounded
__device__ float g_AC[(size_t)NLAYER*HH*256*TCH];     // tf32-rounded
__device__ float g_F[(size_t)HH*JCOLS*128];           // fp32 (scan input)
__device__ float g_S[(size_t)HH*JCOLS*128];           // tf32-rounded
__device__ __half g_Wh[(size_t)NLAYER*G2*HH];         // out_W in fp16
__device__ float g_wTr[NLAYER*HH*NS];
__device__ float g_wTi[NLAYER*HH*NS];

__device__ __forceinline__ unsigned cvt_tf32(float f) {
    unsigned r;
    asm("cvt.rna.tf32.f32 %0, %1;" : "=r"(r) : "f"(f));
    return r;
}
__device__ __forceinline__ float round_tf32(float f) { return __uint_as_float(cvt_tf32(f)); }

__device__ __forceinline__ void mma_tf32(float c[4], const unsigned a[4], unsigned b0, unsigned b1) {
    asm volatile("mma.sync.aligned.m16n8k8.row.col.f32.tf32.tf32.f32 "
                 "{%0,%1,%2,%3}, {%4,%5,%6,%7}, {%8,%9}, {%0,%1,%2,%3};"
                 : "+f"(c[0]), "+f"(c[1]), "+f"(c[2]), "+f"(c[3])
                 : "r"(a[0]), "r"(a[1]), "r"(a[2]), "r"(a[3]), "r"(b0), "r"(b1));
}

__device__ __forceinline__ void mma_f16(float c[4], const unsigned a[4], unsigned b0, unsigned b1) {
    asm volatile("mma.sync.aligned.m16n8k16.row.col.f32.f16.f16.f32 "
                 "{%0,%1,%2,%3}, {%4,%5,%6,%7}, {%8,%9}, {%0,%1,%2,%3};"
                 : "+f"(c[0]), "+f"(c[1]), "+f"(c[2]), "+f"(c[3])
                 : "r"(a[0]), "r"(a[1]), "r"(a[2]), "r"(a[3]), "r"(b0), "r"(b1));
}

__device__ __forceinline__ unsigned pack_h2(float lo, float hi) {
    unsigned r;
    asm("cvt.rn.f16x2.f32 %0, %1, %2;" : "=r"(r) : "f"(hi), "f"(lo));
    return r;
}

__device__ __forceinline__ void cp_async16(float* smem_dst, const float* gmem_src) {
    unsigned s = (unsigned)__cvta_generic_to_shared(smem_dst);
    asm volatile("cp.async.ca.shared.global [%0], [%1], 16;" :: "r"(s), "l"(gmem_src));
}
__device__ __forceinline__ void cp_async16_h(__half* smem_dst, const __half* gmem_src) {
    unsigned s = (unsigned)__cvta_generic_to_shared(smem_dst);
    asm volatile("cp.async.ca.shared.global [%0], [%1], 16;" :: "r"(s), "l"(gmem_src));
}
#define CP_COMMIT() asm volatile("cp.async.commit_group;")
#define CP_WAIT1()  asm volatile("cp.async.wait_group 1;")
#define CP_WAIT0()  asm volatile("cp.async.wait_group 0;")

__device__ __forceinline__ void st_tf32_4(float* dst, float4 v) {
    unsigned* d = (unsigned*)dst;
    d[0] = cvt_tf32(v.x); d[1] = cvt_tf32(v.y);
    d[2] = cvt_tf32(v.z); d[3] = cvt_tf32(v.w);
}

__device__ __forceinline__ float gelu_f(float v) {
    float x3 = v*v*v;
    return 0.5f*v*(1.0f + tanhf(fmaf(0.0356774081f, x3, 0.7978845608f*v)));
}

// ---------------------------------------------------------------------------
__global__ void precompute_kernel(const float* __restrict__ log_dt,
                                  const float* __restrict__ A_log_re,
                                  const float* __restrict__ A_im,
                                  const float* __restrict__ C_re,
                                  const float* __restrict__ C_im) {
    int idx = blockIdx.x * blockDim.x + threadIdx.x;
    if (idx >= NLAYER*HH*NS) return;
    int i = idx / (HH*NS);
    int h = (idx / NS) % HH;
    float dt  = expf(log_dt[i*HH + h]);
    float Are = -expf(A_log_re[idx]);
    float Aim = A_im[idx];
    float er = dt*Are, ei = dt*Aim;
    float mag = expf(er);
    float wr = mag*cosf(ei), wi = mag*sinf(ei);
    float nr = wr - 1.0f, ni = wi;
    float den = Are*Are + Aim*Aim;
    float inv = 1.0f/den;
    float qr = (nr*Are + ni*Aim)*inv;
    float qi = (ni*Are - nr*Aim)*inv;
    float cr = C_re[idx], ci = C_im[idx];
    g_wr[idx] = wr; g_wi[idx] = wi;
    g_cr[idx] = 2.0f*(cr*qr - ci*qi);
    g_ci[idx] = 2.0f*(cr*qi + ci*qr);
}

// ---------------------------------------------------------------------------
__global__ void roundW_kernel(const float* __restrict__ W) {
    int i = blockIdx.x*256 + threadIdx.x;
    g_Wh[i] = __float2half(W[i]);
}

// ---------------------------------------------------------------------------
__global__ void precompute2_kernel() {
    extern __shared__ float ps[];
    float* wpr = ps;
    float* wpi = ps + 129*68;
    float* sK  = wpi + 129*68;
    int tid = threadIdx.x;
    int lh = blockIdx.x;
    int ib = lh*NS;
    if (tid < 64) {
        int n = tid;
        float wr = g_wr[ib+n], wi = g_wi[ib+n];
        float pr = 1.f, pi = 0.f;
        for (int d = 0; d <= 128; d++) {
            wpr[d*68+n] = pr; wpi[d*68+n] = pi;
            float nr = pr*wr - pi*wi;
            float ni = pr*wi + pi*wr;
            pr = nr; pi = ni;
        }
    }
    __syncthreads();
    {
        int d = tid;
        float s = 0.f;
        for (int n = 0; n < 64; n++)
            s += g_cr[ib+n]*wpr[d*68+n] - g_ci[ib+n]*wpi[d*68+n];
        sK[d] = s;
    }
    if (tid < 64) {
        g_wTr[ib+tid] = wpr[128*68+tid];
        g_wTi[ib+tid] = wpi[128*68+tid];
    }
    __syncthreads();
    size_t pbase = (size_t)lh*TCH*128;
    int n2 = tid;
    for (int tau = 0; tau < TCH; tau++) {
        float v = (n2 < 64) ? wpr[(127-tau)*68 + n2] : wpi[(127-tau)*68 + (n2-64)];
        g_P[pbase + (size_t)tau*128 + n2] = round_tf32(v);
    }
    size_t acbase = (size_t)lh*256*TCH;
    int t = tid;
    for (int tau = 0; tau < TCH; tau++)
        g_AC[acbase + (size_t)tau*TCH + t] = (t >= tau) ? round_tf32(sK[t - tau]) : 0.f;
    for (int q2 = 0; q2 < 128; q2++) {
        int n = q2 & 63;
        float cr = g_cr[ib+n], ci = g_ci[ib+n];
        float wr = wpr[(t+1)*68 + n], wi = wpi[(t+1)*68 + n];
        float v = (q2 < 64) ? (cr*wr - ci*wi) : -(cr*wi + ci*wr);
        g_AC[acbase + (size_t)(128 + q2)*TCH + t] = round_tf32(v);
    }
}

// ---------------------------------------------------------------------------
// Embed as tf32 GEMM (R10 version): (B*L,75)@(75,256)+b -> g_hT
// ---------------------------------------------------------------------------
#define EK 80
__global__ void __launch_bounds__(256) embed_tc_kernel(const float* __restrict__ x,
                                                       const float* __restrict__ W,
                                                       const float* __restrict__ bias) {
    extern __shared__ float sm[];
    float* As = sm;              // [128][84]
    float* Bs = sm + 128*84;     // [80][72]
    int tid = threadIdx.x;
    int warp = tid >> 5, lane = tid & 31;
    int wm = warp & 3, wn = warp >> 2;
    int gid = lane >> 2, tig = lane & 3;
    int n0 = blockIdx.x * 64;
    int m0 = blockIdx.y * 128;

    for (int i = tid; i < 128*EK; i += 256) {
        int row = i / EK, k = i % EK;
        float v = (k < FIN) ? x[(size_t)(m0 + row)*FIN + k] : 0.f;
        As[row*84 + k] = __uint_as_float(cvt_tf32(v));
    }
    for (int i = tid; i < EK*64; i += 256) {
        int k = i >> 6, n = i & 63;
        float v = (k < FIN) ? W[k*HH + n0 + n] : 0.f;
        Bs[k*72 + n] = __uint_as_float(cvt_tf32(v));
    }
    __syncthreads();

    float acc[2][4][4];
    #pragma unroll
    for (int i = 0; i < 2; i++)
        #pragma unroll
        for (int j = 0; j < 4; j++)
            #pragma unroll
            for (int q = 0; q < 4; q++) acc[i][j][q] = 0.f;

    #pragma unroll
    for (int k8 = 0; k8 < EK; k8 += 8) {
        unsigned a[2][4];
        #pragma unroll
        for (int m2 = 0; m2 < 2; m2++) {
            int l = wm*32 + m2*16 + gid;
            a[m2][0] = __float_as_uint(As[l*84 + k8 + tig]);
            a[m2][1] = __float_as_uint(As[(l + 8)*84 + k8 + tig]);
            a[m2][2] = __float_as_uint(As[l*84 + k8 + 4 + tig]);
            a[m2][3] = __float_as_uint(As[(l + 8)*84 + k8 + 4 + tig]);
        }
        #pragma unroll
        for (int nt = 0; nt < 4; nt++) {
            int n = wn*32 + nt*8 + gid;
            unsigned b0 = __float_as_uint(Bs[(k8 + tig)*72 + n]);
            unsigned b1 = __float_as_uint(Bs[(k8 + 4 + tig)*72 + n]);
            #pragma unroll
            for (int m2 = 0; m2 < 2; m2++)
                mma_tf32(acc[m2][nt], a[m2], b0, b1);
        }
    }
    #pragma unroll
    for (int m2 = 0; m2 < 2; m2++) {
        #pragma unroll
        for (int nt = 0; nt < 4; nt++) {
            #pragma unroll
            for (int q = 0; q < 4; q++) {
                int row = m0 + wm*32 + m2*16 + gid + ((q >> 1) ? 8 : 0);
                int col = n0 + wn*32 + nt*8 + 2*tig + (q & 1);
                g_hT[(size_t)row*HH + col] = acc[m2][nt][q] + bias[col];
            }
        }
    }
}

// ---------------------------------------------------------------------------
// LayerNorm + transpose; output tf32-rounded.
// ---------------------------------------------------------------------------
__global__ void ln_kernel(const float* __restrict__ gvec,
                          const float* __restrict__ bvec) {
    __shared__ float s[32][HH+1];
    __shared__ float sg[HH], sb[HH];
    int tid = threadIdx.x;
    sg[tid] = gvec[tid]; sb[tid] = bvec[tid];
    int blk = blockIdx.x;
    int b = blk / (LL/32);
    int l0 = (blk % (LL/32)) * 32;
    int warp = tid >> 5, lane = tid & 31;
    __syncthreads();
    for (int tt = 0; tt < 4; tt++) {
        int t = warp*4 + tt;
        const float* p = g_hT + ((size_t)(b*LL + l0 + t))*HH;
        float v[8];
        float sum = 0.f;
        #pragma unroll
        for (int j = 0; j < 8; j++) { v[j] = p[lane + 32*j]; sum += v[j]; }
        #pragma unroll
        for (int o = 16; o; o >>= 1) sum += __shfl_xor_sync(0xffffffffu, sum, o);
        float mean = sum * (1.0f/HH);
        float var = 0.f;
        #pragma unroll
        for (int j = 0; j < 8; j++) { float d = v[j]-mean; var = fmaf(d, d, var); }
        #pragma unroll
        for (int o = 16; o; o >>= 1) var += __shfl_xor_sync(0xffffffffu, var, o);
        float rstd = rsqrtf(var*(1.0f/HH) + 1e-5f);
        #pragma unroll
        for (int j = 0; j < 8; j++) {
            int c = lane + 32*j;
            s[t][c] = (v[j]-mean)*rstd*sg[c] + sb[c];
        }
    }
    __syncthreads();
    #pragma unroll 4
    for (int it = 0; it < 32; it++) {
        int h = it*8 + (tid >> 5);
        int ll = tid & 31;
        g_ucm[((size_t)(b*HH + h))*LL + l0 + ll] = round_tf32(s[ll][h]);
    }
}

// ---------------------------------------------------------------------------
// GEMM-F (R10: 512 thr, cp.async 2-stage): F = U @ P  M=128 N=128 K=128
// ---------------------------------------------------------------------------
__global__ void __launch_bounds__(512) gemm_f_kernel(int layer) {
    extern __shared__ float sm[];
    float* AsB[2] = { sm,            sm + 128*36 };
    float* BsB[2] = { sm + 2*128*36, sm + 2*128*36 + 32*136 };
    int tid = threadIdx.x;
    int warp = tid >> 5, lane = tid & 31;
    int wm = warp & 3, wn = warp >> 2;
    int gid = lane >> 2, tig = lane & 3;
    int h = blockIdx.y;
    int j0 = blockIdx.x * 128;
    const float* P = g_P + (size_t)(layer*HH + h)*TCH*128;

    int a_row = tid >> 3, a_kq = tid & 7;
    int a_row2 = (tid + 512) >> 3, a_kq2 = (tid + 512) & 7;
    int b_k = tid >> 5, b_tq = tid & 31;
    int jA = j0 + a_row;
    size_t abase0 = ((size_t)((jA & 15)*HH + h))*LL + (jA >> 4)*TCH + a_kq*4;
    int jA2 = j0 + a_row2;
    size_t abase1 = ((size_t)((jA2 & 15)*HH + h))*LL + (jA2 >> 4)*TCH + a_kq2*4;

    float acc[2][4][4];
    #pragma unroll
    for (int i = 0; i < 2; i++)
        #pragma unroll
        for (int j = 0; j < 4; j++)
            #pragma unroll
            for (int q = 0; q < 4; q++) acc[i][j][q] = 0.f;

#define GF_ISSUE(k0, buf) { \
    cp_async16(&AsB[buf][a_row*36 + a_kq*4],   &g_ucm[abase0 + (k0)]); \
    cp_async16(&AsB[buf][a_row2*36 + a_kq2*4], &g_ucm[abase1 + (k0)]); \
    cp_async16(&BsB[buf][b_k*136 + b_tq*4],        &P[(size_t)((k0) + b_k)*128 + b_tq*4]); \
    cp_async16(&BsB[buf][(16 + b_k)*136 + b_tq*4], &P[(size_t)((k0) + 16 + b_k)*128 + b_tq*4]); \
    CP_COMMIT(); }

    GF_ISSUE(0, 0);
    for (int c = 0; c < 4; c++) {
        if (c < 3) { GF_ISSUE((c+1)*32, (c+1)&1); CP_WAIT1(); } else { CP_WAIT0(); }
        __syncthreads();
        float* As = AsB[c & 1];
        float* Bs = BsB[c & 1];
        #pragma unroll
        for (int k8 = 0; k8 < 32; k8 += 8) {
            unsigned a[2][4];
            #pragma unroll
            for (int m2 = 0; m2 < 2; m2++) {
                int l = wm*32 + m2*16 + gid;
                a[m2][0] = __float_as_uint(As[l*36 + k8 + tig]);
                a[m2][1] = __float_as_uint(As[(l + 8)*36 + k8 + tig]);
                a[m2][2] = __float_as_uint(As[l*36 + k8 + 4 + tig]);
                a[m2][3] = __float_as_uint(As[(l + 8)*36 + k8 + 4 + tig]);
            }
            #pragma unroll
            for (int nt = 0; nt < 4; nt++) {
                int n = wn*32 + nt*8 + gid;
                unsigned b0 = __float_as_uint(Bs[(k8 + tig)*136 + n]);
                unsigned b1 = __float_as_uint(Bs[(k8 + 4 + tig)*136 + n]);
                #pragma unroll
                for (int m2 = 0; m2 < 2; m2++)
                    mma_tf32(acc[m2][nt], a[m2], b0, b1);
            }
        }
        __syncthreads();
    }
    #pragma unroll
    for (int m2 = 0; m2 < 2; m2++) {
        #pragma unroll
        for (int nt = 0; nt < 4; nt++) {
            #pragma unroll
            for (int q = 0; q < 4; q++) {
                int row = wm*32 + m2*16 + gid + ((q >> 1) ? 8 : 0);
                int col = wn*32 + nt*8 + 2*tig + (q & 1);
                g_F[((size_t)h*JCOLS + j0 + row)*128 + col] = acc[m2][nt][q];
            }
        }
    }
}

// ---------------------------------------------------------------------------
__global__ void chunkscan_kernel(int layer) {
    int g = blockIdx.x*256 + threadIdx.x;
    int h = g >> 10;
    int r = g & 1023;
    int bb = r >> 6;
    int n = r & 63;
    int ib = (layer*HH + h)*NS + n;
    float wtr = g_wTr[ib], wti = g_wTi[ib];
    float sre = 0.f, sim = 0.f;
    size_t base = (size_t)h*JCOLS*128;
    #pragma unroll
    for (int c = 0; c < NCHUNK; c++) {
        size_t jo = base + (size_t)(c*16 + bb)*128;
        g_S[jo + n]      = round_tf32(sre);
        g_S[jo + 64 + n] = round_tf32(sim);
        float fre = g_F[jo + n];
        float fim = g_F[jo + 64 + n];
        float nr = fmaf(wtr, sre, fmaf(-wti, sim, fre));
        float ni = fmaf(wtr, sim, fmaf(wti, sre, fim));
        sre = nr; sim = ni;
    }
}

// ---------------------------------------------------------------------------
// GEMM-Y (R10: 512 thr, cp.async 2-stage): y = [U|S] @ AC  M=128 N=128 K=256
// ---------------------------------------------------------------------------
__global__ void __launch_bounds__(512) gemm_y_kernel(int layer, const float* __restrict__ Dski) {
    extern __shared__ float sm[];
    float* AsB[2] = { sm,            sm + 128*36 };
    float* BsB[2] = { sm + 2*128*36, sm + 2*128*36 + 32*136 };
    int tid = threadIdx.x;
    int warp = tid >> 5, lane = tid & 31;
    int wm = warp & 3, wn = warp >> 2;
    int gid = lane >> 2, tig = lane & 3;
    int h = blockIdx.y;
    int j0 = blockIdx.x * 128;
    const float* AC = g_AC + (size_t)(layer*HH + h)*256*TCH;

    int b_k = tid >> 5, b_tq = tid & 31;
    int rowA0 = tid >> 3, kqA0 = tid & 7;
    int rowA1 = (tid + 512) >> 3, kqA1 = (tid + 512) & 7;
    int jA0 = j0 + rowA0, jA1 = j0 + rowA1;
    size_t ubase0 = ((size_t)((jA0 & 15)*HH + h))*LL + (jA0 >> 4)*TCH + kqA0*4;
    size_t ubase1 = ((size_t)((jA1 & 15)*HH + h))*LL + (jA1 >> 4)*TCH + kqA1*4;
    size_t sbase0 = ((size_t)h*JCOLS + jA0)*128 + kqA0*4;
    size_t sbase1 = ((size_t)h*JCOLS + jA1)*128 + kqA1*4;

    float acc[2][4][4];
    #pragma unroll
    for (int i = 0; i < 2; i++)
        #pragma unroll
        for (int j = 0; j < 4; j++)
            #pragma unroll
            for (int q = 0; q < 4; q++) acc[i][j][q] = 0.f;

#define GY_ISSUE(k0, buf) { \
    const float* s0 = ((k0) < TCH) ? &g_ucm[ubase0 + (k0)] : &g_S[sbase0 + (k0) - TCH]; \
    const float* s1 = ((k0) < TCH) ? &g_ucm[ubase1 + (k0)] : &g_S[sbase1 + (k0) - TCH]; \
    cp_async16(&AsB[buf][rowA0*36 + kqA0*4], s0); \
    cp_async16(&AsB[buf][rowA1*36 + kqA1*4], s1); \
    cp_async16(&BsB[buf][b_k*136 + b_tq*4],        &AC[(size_t)((k0) + b_k)*TCH + b_tq*4]); \
    cp_async16(&BsB[buf][(16 + b_k)*136 + b_tq*4], &AC[(size_t)((k0) + 16 + b_k)*TCH + b_tq*4]); \
    CP_COMMIT(); }

    GY_ISSUE(0, 0);
    for (int c = 0; c < 8; c++) {
        if (c < 7) { GY_ISSUE((c+1)*32, (c+1)&1); CP_WAIT1(); } else { CP_WAIT0(); }
        __syncthreads();
        float* As = AsB[c & 1];
        float* Bs = BsB[c & 1];
        #pragma unroll
        for (int k8 = 0; k8 < 32; k8 += 8) {
            unsigned a[2][4];
            #pragma unroll
            for (int m2 = 0; m2 < 2; m2++) {
                int l = wm*32 + m2*16 + gid;
                a[m2][0] = __float_as_uint(As[l*36 + k8 + tig]);
                a[m2][1] = __float_as_uint(As[(l + 8)*36 + k8 + tig]);
                a[m2][2] = __float_as_uint(As[l*36 + k8 + 4 + tig]);
                a[m2][3] = __float_as_uint(As[(l + 8)*36 + k8 + 4 + tig]);
            }
            #pragma unroll
            for (int nt = 0; nt < 4; nt++) {
                int n = wn*32 + nt*8 + gid;
                unsigned b0 = __float_as_uint(Bs[(k8 + tig)*136 + n]);
                unsigned b1 = __float_as_uint(Bs[(k8 + 4 + tig)*136 + n]);
                #pragma unroll
                for (int m2 = 0; m2 < 2; m2++)
                    mma_tf32(acc[m2][nt], a[m2], b0, b1);
            }
        }
        __syncthreads();
    }
    float D = Dski[h];
    #pragma unroll
    for (int m2 = 0; m2 < 2; m2++) {
        #pragma unroll
        for (int nt = 0; nt < 4; nt++) {
            #pragma unroll
            for (int q = 0; q < 4; q++) {
                int row = wm*32 + m2*16 + gid + ((q >> 1) ? 8 : 0);
                int j = j0 + row;
                int t = wn*32 + nt*8 + 2*tig + (q & 1);
                int c = j >> 4, bb = j & 15;
                size_t base = ((size_t)(bb*HH + h))*LL + c*TCH;
                float u = g_ucm[base + t];
                float yv = fmaf(D, u, acc[m2][nt][q]);
                g_ycm[base + t] = round_tf32(gelu_f(yv));
            }
        }
    }
}

// ---------------------------------------------------------------------------
// GLU via fp16 mma.sync.m16n8k16:
//   M = 128 tokens (A = Y, transposed to [l][k] half during staging)
//   N = 64 g-cols for z1 + paired z2 (B = W in fp16, [g][k])
//   K = 256 in 8 chunks of 32. Single-buffered, fp32 accumulate.
// ---------------------------------------------------------------------------
__global__ void __launch_bounds__(256) glu_f16_kernel(int layer, const float* __restrict__ bias) {
    __shared__ __half As_h[128*44];    // [l][k], stride 44 halves
    __shared__ __half Bs1_h[64*40];    // [g][k], stride 40 halves
    __shared__ __half Bs2_h[64*40];
    int tid = threadIdx.x;
    int warp = tid >> 5, lane = tid & 31;
    int wm = warp & 3, wn = warp >> 2;
    int gid = lane >> 2, tig = lane & 3;
    int g0 = blockIdx.x * 64;
    int mt = blockIdx.y;
    int b  = mt >> 4;
    int l0 = (mt & 15) * 128;
    const __half* Wh = g_Wh + (size_t)layer * G2 * HH;

    float acc1[2][4][4], acc2[2][4][4];
    #pragma unroll
    for (int i = 0; i < 2; i++)
        #pragma unroll
        for (int j = 0; j < 4; j++)
            #pragma unroll
            for (int q = 0; q < 4; q++) { acc1[i][j][q] = 0.f; acc2[i][j][q] = 0.f; }

    for (int c = 0; c < 8; c++) {
        int k0 = c * 32;
        // Stage A: Y [k][l] fp32 -> As_h [l][k] half. Each item: 4 rows of same l.
        #pragma unroll
        for (int it = 0; it < 4; it++) {
            int e = tid + it*256;            // 0..1023
            int l = e & 127, kk0 = (e >> 7) * 4;
            size_t gb = ((size_t)(b*HH + k0 + kk0))*LL + l0 + l;
            float v0 = g_ycm[gb];
            float v1 = g_ycm[gb + LL];
            float v2 = g_ycm[gb + 2*LL];
            float v3 = g_ycm[gb + 3*LL];
            uint2 pk = make_uint2(pack_h2(v0, v1), pack_h2(v2, v3));
            *(uint2*)&As_h[l*44 + kk0] = pk;
        }
        // Stage B: W halves [g][k] via cp.async (16B = 8 halves per op).
        #pragma unroll
        for (int it = 0; it < 2; it++) {
            int e = tid + it*256;            // 0..511
            int mat = e >> 8, r = e & 255;
            int gg = r >> 2, kq = r & 3;
            const __half* src = &Wh[(size_t)((mat ? (256 + g0) : g0) + gg)*HH + k0 + kq*8];
            __half* dst = (mat ? Bs2_h : Bs1_h) + gg*40 + kq*8;
            cp_async16_h(dst, src);
        }
        CP_COMMIT();
        CP_WAIT0();
        __syncthreads();

        #pragma unroll
        for (int k16 = 0; k16 < 32; k16 += 16) {
            unsigned a[2][4];
            #pragma unroll
            for (int m2 = 0; m2 < 2; m2++) {
                int l = wm*32 + m2*16 + gid;
                a[m2][0] = *(const unsigned*)&As_h[l*44 + k16 + 2*tig];
                a[m2][1] = *(const unsigned*)&As_h[(l + 8)*44 + k16 + 2*tig];
                a[m2][2] = *(const unsigned*)&As_h[l*44 + k16 + 8 + 2*tig];
                a[m2][3] = *(const unsigned*)&As_h[(l + 8)*44 + k16 + 8 + 2*tig];
            }
            #pragma unroll
            for (int nt = 0; nt < 4; nt++) {
                int n = wn*32 + nt*8 + gid;
                unsigned b10 = *(const unsigned*)&Bs1_h[n*40 + k16 + 2*tig];
                unsigned b11 = *(const unsigned*)&Bs1_h[n*40 + k16 + 8 + 2*tig];
                unsigned b20 = *(const unsigned*)&Bs2_h[n*40 + k16 + 2*tig];
                unsigned b21 = *(const unsigned*)&Bs2_h[n*40 + k16 + 8 + 2*tig];
                #pragma unroll
                for (int m2 = 0; m2 < 2; m2++) {
                    mma_f16(acc1[m2][nt], a[m2], b10, b11);
                    mma_f16(acc2[m2][nt], a[m2], b20, b21);
                }
            }
        }
        __syncthreads();
    }
    #pragma unroll
    for (int m2 = 0; m2 < 2; m2++) {
        #pragma unroll
        for (int nt = 0; nt < 4; nt++) {
            #pragma unroll
            for (int q = 0; q < 4; q++) {
                int row = l0 + wm*32 + m2*16 + gid + ((q >> 1) ? 8 : 0);
                int col = g0 + wn*32 + nt*8 + 2*tig + (q & 1);
                float z1 = acc1[m2][nt][q] + bias[col];
                float z2 = acc2[m2][nt][q] + bias[col + 256];
                float sig = 1.0f/(1.0f + expf(-z2));
                g_hT[((size_t)(b*LL + row))*HH + col] += z1*sig;
            }
        }
    }
}

// ---------------------------------------------------------------------------
// Decoder (R10 synchronous): (B*L,256)@(256,512)+b -> out
// ---------------------------------------------------------------------------
__global__ void __launch_bounds__(256) dec_tc_kernel(const float* __restrict__ W,
                                                     const float* __restrict__ bias,
                                                     float* __restrict__ out) {
    __shared__ float As[128*36];
    __shared__ float Bs[32*72];
    int tid = threadIdx.x;
    int warp = tid >> 5, lane = tid & 31;
    int wm = warp & 3, wn = warp >> 2;
    int gid = lane >> 2, tig = lane & 3;
    int r0 = blockIdx.x * 64;
    int m0 = blockIdx.y * 128;

    float acc[2][4][4];
    #pragma unroll
    for (int i = 0; i < 2; i++)
        #pragma unroll
        for (int j = 0; j < 4; j++)
            #pragma unroll
            for (int q = 0; q < 4; q++) acc[i][j][q] = 0.f;

    for (int k0 = 0; k0 < HH; k0 += 32) {
        #pragma unroll
        for (int i = 0; i < 4; i++) {
            int f4 = tid + i*256;
            int l = f4 >> 3, kq = f4 & 7;
            float4 v = *(const float4*)&g_hT[((size_t)(m0 + l))*HH + k0 + kq*4];
            st_tf32_4(&As[l*36 + kq*4], v);
        }
        #pragma unroll
        for (int i = 0; i < 2; i++) {
            int f4 = tid + i*256;
            int kk = f4 >> 4, rq = f4 & 15;
            float4 v = *(const float4*)&W[(size_t)(k0 + kk)*REPR + r0 + rq*4];
            st_tf32_4(&Bs[kk*72 + rq*4], v);
        }
        __syncthreads();
        #pragma unroll
        for (int k8 = 0; k8 < 32; k8 += 8) {
            unsigned a[2][4];
            #pragma unroll
            for (int m2 = 0; m2 < 2; m2++) {
                int l = wm*32 + m2*16 + gid;
                a[m2][0] = __float_as_uint(As[l*36 + k8 + tig]);
                a[m2][1] = __float_as_uint(As[(l + 8)*36 + k8 + tig]);
                a[m2][2] = __float_as_uint(As[l*36 + k8 + 4 + tig]);
                a[m2][3] = __float_as_uint(As[(l + 8)*36 + k8 + 4 + tig]);
            }
            #pragma unroll
            for (int nt = 0; nt < 4; nt++) {
                int n = wn*32 + nt*8 + gid;
                unsigned b0 = __float_as_uint(Bs[(k8 + tig)*72 + n]);
                unsigned b1 = __float_as_uint(Bs[(k8 + 4 + tig)*72 + n]);
                #pragma unroll
                for (int m2 = 0; m2 < 2; m2++)
                    mma_tf32(acc[m2][nt], a[m2], b0, b1);
            }
        }
        __syncthreads();
    }
    #pragma unroll
    for (int m2 = 0; m2 < 2; m2++) {
        #pragma unroll
        for (int nt = 0; nt < 4; nt++) {
            #pragma unroll
            for (int q = 0; q < 4; q++) {
                int row = m0 + wm*32 + m2*16 + gid + ((q >> 1) ? 8 : 0);
                int col = r0 + wn*32 + nt*8 + 2*tig + (q & 1);
                out[(size_t)row*REPR + col] = acc[m2][nt][q] + bias[col];
            }
        }
    }
}

// ---------------------------------------------------------------------------
extern "C" void kernel_launch(void* const* d_in, const int* in_sizes, int n_in,
                              void* d_out, int out_size) {
    const float* x        = (const float*)d_in[0];
    const float* embed_W  = (const float*)d_in[1];
    const float* embed_b  = (const float*)d_in[2];
    const float* log_dt   = (const float*)d_in[3];
    const float* A_log_re = (const float*)d_in[4];
    const float* A_im     = (const float*)d_in[5];
    const float* C_re     = (const float*)d_in[6];
    const float* C_im     = (const float*)d_in[7];
    const float* D_skip   = (const float*)d_in[8];
    const float* out_W    = (const float*)d_in[9];
    const float* out_b    = (const float*)d_in[10];
    const float* ln_g     = (const float*)d_in[11];
    const float* ln_b     = (const float*)d_in[12];
    const float* dec_W    = (const float*)d_in[13];
    const float* dec_b    = (const float*)d_in[14];
    float* out = (float*)d_out;

    const int PRE2_SMEM = (2*129*68 + 128) * sizeof(float);
    const int EMB_SMEM = (128*84 + EK*72) * sizeof(float);        // 66048
    const int GF_SMEM  = (2*128*36 + 2*32*136) * sizeof(float);   // 71680
    const int GY_SMEM  = GF_SMEM;
    static int smem_set = 0;
    if (!smem_set) {
        cudaFuncSetAttribute(embed_tc_kernel, cudaFuncAttributeMaxDynamicSharedMemorySize, EMB_SMEM);
        cudaFuncSetAttribute(precompute2_kernel, cudaFuncAttributeMaxDynamicSharedMemorySize,
                             PRE2_SMEM);
        cudaFuncSetAttribute(gemm_f_kernel, cudaFuncAttributeMaxDynamicSharedMemorySize, GF_SMEM);
        cudaFuncSetAttribute(gemm_y_kernel, cudaFuncAttributeMaxDynamicSharedMemorySize, GY_SMEM);
        smem_set = 1;
    }

    precompute_kernel<<<(NLAYER*HH*NS + 255)/256, 256>>>(log_dt, A_log_re, A_im, C_re, C_im);
    precompute2_kernel<<<NLAYER*HH, 128, PRE2_SMEM>>>();
    roundW_kernel<<<NLAYER*G2*HH/256, 256>>>(out_W);
    embed_tc_kernel<<<dim3(4, BB*LL/128), 256, EMB_SMEM>>>(x, embed_W, embed_b);
    for (int i = 0; i < NLAYER; i++) {
        ln_kernel<<<BB*LL/32, 256>>>(ln_g + i*HH, ln_b + i*HH);
        gemm_f_kernel<<<dim3(2, HH), 512, GF_SMEM>>>(i);
        chunkscan_kernel<<<HH*BB*NS/256, 256>>>(i);
        gemm_y_kernel<<<dim3(2, HH), 512, GY_SMEM>>>(i, D_skip + i*HH);
        glu_f16_kernel<<<dim3(4, BB*LL/128), 256>>>(i, out_b + i*G2);
    }
    dec_tc_kernel<<<dim3(REPR/64, BB*LL/128), 256>>>(dec_W, dec_b, out);
}

// round 15
// speedup vs baseline: 1.2847x; 1.2169x over previous
#include <cuda_runtime.h>
#include <cuda_fp16.h>
#include <stdint.h>
#include <math.h>

#define BB 16
#define LL 2048
#define HH 256
#define NS 64
#define NLAYER 4
#define FIN 75
#define G2 512
#define REPR 512
#define TCH 128      // chunk length
#define NCHUNK 16    // LL/TCH
#define JCOLS 256    // NCHUNK*BB

// ---- device scratch ----
__device__ float  g_hT[BB*LL*HH];      // residual stream, token-major (fp32)
__device__ __half g_ucmh[BB*HH*LL];    // LN output, channel-major (fp16)
__device__ float  g_ycm[BB*HH*LL];     // scan output (tf32-rounded fp32)
__device__ float  g_wr[NLAYER*HH*NS];
__device__ float  g_wi[NLAYER*HH*NS];
__device__ float  g_cr[NLAYER*HH*NS];
__device__ float  g_ci[NLAYER*HH*NS];
__device__ __half g_PTh[(size_t)NLAYER*HH*128*TCH];   // P^T [n2][tau] fp16
__device__ __half g_ACTh[(size_t)NLAYER*HH*TCH*256];  // AC^T [t][k] fp16
__device__ float  g_F[(size_t)HH*JCOLS*128];          // fp32 (scan input)
__device__ __half g_Sh[(size_t)HH*JCOLS*128];         // chunk states fp16
__device__ __half g_Wh[(size_t)NLAYER*G2*HH];         // out_W fp16
__device__ __half g_Wdh[(size_t)REPR*HH];             // dec_W^T [r][k] fp16
__device__ float  g_wTr[NLAYER*HH*NS];
__device__ float  g_wTi[NLAYER*HH*NS];

__device__ __forceinline__ unsigned cvt_tf32(float f) {
    unsigned r;
    asm("cvt.rna.tf32.f32 %0, %1;" : "=r"(r) : "f"(f));
    return r;
}
__device__ __forceinline__ float round_tf32(float f) { return __uint_as_float(cvt_tf32(f)); }

__device__ __forceinline__ void mma_tf32(float c[4], const unsigned a[4], unsigned b0, unsigned b1) {
    asm volatile("mma.sync.aligned.m16n8k8.row.col.f32.tf32.tf32.f32 "
                 "{%0,%1,%2,%3}, {%4,%5,%6,%7}, {%8,%9}, {%0,%1,%2,%3};"
                 : "+f"(c[0]), "+f"(c[1]), "+f"(c[2]), "+f"(c[3])
                 : "r"(a[0]), "r"(a[1]), "r"(a[2]), "r"(a[3]), "r"(b0), "r"(b1));
}

__device__ __forceinline__ void mma_f16(float c[4], const unsigned a[4], unsigned b0, unsigned b1) {
    asm volatile("mma.sync.aligned.m16n8k16.row.col.f32.f16.f16.f32 "
                 "{%0,%1,%2,%3}, {%4,%5,%6,%7}, {%8,%9}, {%0,%1,%2,%3};"
                 : "+f"(c[0]), "+f"(c[1]), "+f"(c[2]), "+f"(c[3])
                 : "r"(a[0]), "r"(a[1]), "r"(a[2]), "r"(a[3]), "r"(b0), "r"(b1));
}

__device__ __forceinline__ unsigned pack_h2(float lo, float hi) {
    unsigned r;
    asm("cvt.rn.f16x2.f32 %0, %1, %2;" : "=r"(r) : "f"(hi), "f"(lo));
    return r;
}

__device__ __forceinline__ void cp_async16(float* smem_dst, const float* gmem_src) {
    unsigned s = (unsigned)__cvta_generic_to_shared(smem_dst);
    asm volatile("cp.async.ca.shared.global [%0], [%1], 16;" :: "r"(s), "l"(gmem_src));
}
__device__ __forceinline__ void cp_async16_h(__half* smem_dst, const __half* gmem_src) {
    unsigned s = (unsigned)__cvta_generic_to_shared(smem_dst);
    asm volatile("cp.async.ca.shared.global [%0], [%1], 16;" :: "r"(s), "l"(gmem_src));
}
#define CP_COMMIT() asm volatile("cp.async.commit_group;")
#define CP_WAIT1()  asm volatile("cp.async.wait_group 1;")
#define CP_WAIT0()  asm volatile("cp.async.wait_group 0;")

__device__ __forceinline__ float gelu_f(float v) {
    float x3 = v*v*v;
    return 0.5f*v*(1.0f + tanhf(fmaf(0.0356774081f, x3, 0.7978845608f*v)));
}

// ---------------------------------------------------------------------------
__global__ void precompute_kernel(const float* __restrict__ log_dt,
                                  const float* __restrict__ A_log_re,
                                  const float* __restrict__ A_im,
                                  const float* __restrict__ C_re,
                                  const float* __restrict__ C_im) {
    int idx = blockIdx.x * blockDim.x + threadIdx.x;
    if (idx >= NLAYER*HH*NS) return;
    int i = idx / (HH*NS);
    int h = (idx / NS) % HH;
    float dt  = expf(log_dt[i*HH + h]);
    float Are = -expf(A_log_re[idx]);
    float Aim = A_im[idx];
    float er = dt*Are, ei = dt*Aim;
    float mag = expf(er);
    float wr = mag*cosf(ei), wi = mag*sinf(ei);
    float nr = wr - 1.0f, ni = wi;
    float den = Are*Are + Aim*Aim;
    float inv = 1.0f/den;
    float qr = (nr*Are + ni*Aim)*inv;
    float qi = (ni*Are - nr*Aim)*inv;
    float cr = C_re[idx], ci = C_im[idx];
    g_wr[idx] = wr; g_wi[idx] = wi;
    g_cr[idx] = 2.0f*(cr*qr - ci*qi);
    g_ci[idx] = 2.0f*(cr*qi + ci*qr);
}

// ---------------------------------------------------------------------------
__global__ void roundW_kernel(const float* __restrict__ W) {
    int i = blockIdx.x*256 + threadIdx.x;
    g_Wh[i] = __float2half(W[i]);
}

// dec_W [HH][REPR] -> g_Wdh [r][k] fp16 (one-time transpose, coalesced writes)
__global__ void decWT_kernel(const float* __restrict__ W) {
    int r = blockIdx.x;           // 0..511
    int k = threadIdx.x;          // 0..255
    g_Wdh[(size_t)r*HH + k] = __float2half(W[(size_t)k*REPR + r]);
}

// ---------------------------------------------------------------------------
// Precompute PT (P^T) and ACT (AC^T) in fp16, plus w^T. Coalesced writes.
// ---------------------------------------------------------------------------
__global__ void precompute2_kernel() {
    extern __shared__ float ps[];
    float* wpr = ps;
    float* wpi = ps + 129*68;
    float* sK  = wpi + 129*68;
    int tid = threadIdx.x;                     // 128 threads
    int lh = blockIdx.x;
    int ib = lh*NS;
    if (tid < 64) {
        int n = tid;
        float wr = g_wr[ib+n], wi = g_wi[ib+n];
        float pr = 1.f, pi = 0.f;
        for (int d = 0; d <= 128; d++) {
            wpr[d*68+n] = pr; wpi[d*68+n] = pi;
            float nr = pr*wr - pi*wi;
            float ni = pr*wi + pi*wr;
            pr = nr; pi = ni;
        }
    }
    __syncthreads();
    {
        int d = tid;
        float s = 0.f;
        for (int n = 0; n < 64; n++)
            s += g_cr[ib+n]*wpr[d*68+n] - g_ci[ib+n]*wpi[d*68+n];
        sK[d] = s;
    }
    if (tid < 64) {
        g_wTr[ib+tid] = wpr[128*68+tid];
        g_wTi[ib+tid] = wpi[128*68+tid];
    }
    __syncthreads();
    // PT[n2][tau], tau = tid (coalesced)
    size_t ptb = (size_t)lh*128*TCH;
    int tau = tid;
    for (int n2 = 0; n2 < 128; n2++) {
        float v = (n2 < 64) ? wpr[(127-tau)*68 + n2] : wpi[(127-tau)*68 + (n2-64)];
        g_PTh[ptb + (size_t)n2*TCH + tau] = __float2half(v);
    }
    // ACT[t][k], k in {tid, 128+tid} (coalesced)
    size_t actb = (size_t)lh*TCH*256;
    int n = tid & 63;
    float cr2 = g_cr[ib+n], ci2 = g_ci[ib+n];
    for (int t = 0; t < TCH; t++) {
        int k1 = tid;   // Kmat part
        float v1 = (t >= k1) ? sK[t - k1] : 0.f;
        g_ACTh[actb + (size_t)t*256 + k1] = __float2half(v1);
        int q2 = tid;   // Q part
        float wr2 = wpr[(t+1)*68 + n], wi2 = wpi[(t+1)*68 + n];
        float v2 = (q2 < 64) ? (cr2*wr2 - ci2*wi2) : -(cr2*wi2 + ci2*wr2);
        g_ACTh[actb + (size_t)t*256 + 128 + q2] = __float2half(v2);
    }
}

// ---------------------------------------------------------------------------
// Embed as tf32 GEMM (unchanged): (B*L,75)@(75,256)+b -> g_hT
// ---------------------------------------------------------------------------
#define EK 80
__global__ void __launch_bounds__(256) embed_tc_kernel(const float* __restrict__ x,
                                                       const float* __restrict__ W,
                                                       const float* __restrict__ bias) {
    extern __shared__ float sm[];
    float* As = sm;              // [128][84]
    float* Bs = sm + 128*84;     // [80][72]
    int tid = threadIdx.x;
    int warp = tid >> 5, lane = tid & 31;
    int wm = warp & 3, wn = warp >> 2;
    int gid = lane >> 2, tig = lane & 3;
    int n0 = blockIdx.x * 64;
    int m0 = blockIdx.y * 128;

    for (int i = tid; i < 128*EK; i += 256) {
        int row = i / EK, k = i % EK;
        float v = (k < FIN) ? x[(size_t)(m0 + row)*FIN + k] : 0.f;
        As[row*84 + k] = __uint_as_float(cvt_tf32(v));
    }
    for (int i = tid; i < EK*64; i += 256) {
        int k = i >> 6, n = i & 63;
        float v = (k < FIN) ? W[k*HH + n0 + n] : 0.f;
        Bs[k*72 + n] = __uint_as_float(cvt_tf32(v));
    }
    __syncthreads();

    float acc[2][4][4];
    #pragma unroll
    for (int i = 0; i < 2; i++)
        #pragma unroll
        for (int j = 0; j < 4; j++)
            #pragma unroll
            for (int q = 0; q < 4; q++) acc[i][j][q] = 0.f;

    #pragma unroll
    for (int k8 = 0; k8 < EK; k8 += 8) {
        unsigned a[2][4];
        #pragma unroll
        for (int m2 = 0; m2 < 2; m2++) {
            int l = wm*32 + m2*16 + gid;
            a[m2][0] = __float_as_uint(As[l*84 + k8 + tig]);
            a[m2][1] = __float_as_uint(As[(l + 8)*84 + k8 + tig]);
            a[m2][2] = __float_as_uint(As[l*84 + k8 + 4 + tig]);
            a[m2][3] = __float_as_uint(As[(l + 8)*84 + k8 + 4 + tig]);
        }
        #pragma unroll
        for (int nt = 0; nt < 4; nt++) {
            int n = wn*32 + nt*8 + gid;
            unsigned b0 = __float_as_uint(Bs[(k8 + tig)*72 + n]);
            unsigned b1 = __float_as_uint(Bs[(k8 + 4 + tig)*72 + n]);
            #pragma unroll
            for (int m2 = 0; m2 < 2; m2++)
                mma_tf32(acc[m2][nt], a[m2], b0, b1);
        }
    }
    #pragma unroll
    for (int m2 = 0; m2 < 2; m2++) {
        #pragma unroll
        for (int nt = 0; nt < 4; nt++) {
            #pragma unroll
            for (int q = 0; q < 4; q++) {
                int row = m0 + wm*32 + m2*16 + gid + ((q >> 1) ? 8 : 0);
                int col = n0 + wn*32 + nt*8 + 2*tig + (q & 1);
                g_hT[(size_t)row*HH + col] = acc[m2][nt][q] + bias[col];
            }
        }
    }
}

// ---------------------------------------------------------------------------
// LayerNorm + transpose; output fp16 channel-major.
// ---------------------------------------------------------------------------
__global__ void ln_kernel(const float* __restrict__ gvec,
                          const float* __restrict__ bvec) {
    __shared__ float s[32][HH+1];
    __shared__ float sg[HH], sb[HH];
    int tid = threadIdx.x;
    sg[tid] = gvec[tid]; sb[tid] = bvec[tid];
    int blk = blockIdx.x;
    int b = blk / (LL/32);
    int l0 = (blk % (LL/32)) * 32;
    int warp = tid >> 5, lane = tid & 31;
    __syncthreads();
    for (int tt = 0; tt < 4; tt++) {
        int t = warp*4 + tt;
        const float* p = g_hT + ((size_t)(b*LL + l0 + t))*HH;
        float v[8];
        float sum = 0.f;
        #pragma unroll
        for (int j = 0; j < 8; j++) { v[j] = p[lane + 32*j]; sum += v[j]; }
        #pragma unroll
        for (int o = 16; o; o >>= 1) sum += __shfl_xor_sync(0xffffffffu, sum, o);
        float mean = sum * (1.0f/HH);
        float var = 0.f;
        #pragma unroll
        for (int j = 0; j < 8; j++) { float d = v[j]-mean; var = fmaf(d, d, var); }
        #pragma unroll
        for (int o = 16; o; o >>= 1) var += __shfl_xor_sync(0xffffffffu, var, o);
        float rstd = rsqrtf(var*(1.0f/HH) + 1e-5f);
        #pragma unroll
        for (int j = 0; j < 8; j++) {
            int c = lane + 32*j;
            s[t][c] = (v[j]-mean)*rstd*sg[c] + sb[c];
        }
    }
    __syncthreads();
    #pragma unroll 4
    for (int it = 0; it < 32; it++) {
        int h = it*8 + (tid >> 5);
        int ll = tid & 31;
        g_ucmh[((size_t)(b*HH + h))*LL + l0 + ll] = __float2half(s[ll][h]);
    }
}

// ---------------------------------------------------------------------------
// GEMM-F fp16 (cp.async 2-stage, 256 thr, warp 32mx64n):
//   F[j][n2] = U[j][tau] @ PT[n2][tau]^T   M=128 N=128 K=128
// ---------------------------------------------------------------------------
__global__ void __launch_bounds__(256) gemm_f_kernel(int layer) {
    extern __shared__ __half smh[];
    __half* AsB[2] = { smh,            smh + 128*40 };
    __half* BsB[2] = { smh + 2*128*40, smh + 3*128*40 };
    int tid = threadIdx.x;
    int warp = tid >> 5, lane = tid & 31;
    int wm = warp & 3, wn = warp >> 2;
    int gid = lane >> 2, tig = lane & 3;
    int h = blockIdx.y;
    int j0 = blockIdx.x * 128;
    const __half* PT = g_PTh + (size_t)(layer*HH + h)*128*TCH;

    int ar[2], akq[2];
    size_t ab[2];
    #pragma unroll
    for (int i = 0; i < 2; i++) {
        int idx = tid + i*256;
        ar[i] = idx >> 2; akq[i] = idx & 3;
        int jA = j0 + ar[i];
        ab[i] = ((size_t)((jA & 15)*HH + h))*LL + (jA >> 4)*TCH + akq[i]*8;
    }

    float acc[2][8][4];
    #pragma unroll
    for (int i = 0; i < 2; i++)
        #pragma unroll
        for (int j = 0; j < 8; j++)
            #pragma unroll
            for (int q = 0; q < 4; q++) acc[i][j][q] = 0.f;

#define GF_ISSUE(k0, buf) { \
    _Pragma("unroll") \
    for (int i = 0; i < 2; i++) { \
        cp_async16_h(&AsB[buf][ar[i]*40 + akq[i]*8], &g_ucmh[ab[i] + (k0)]); \
        cp_async16_h(&BsB[buf][ar[i]*40 + akq[i]*8], &PT[(size_t)ar[i]*TCH + (k0) + akq[i]*8]); } \
    CP_COMMIT(); }

    GF_ISSUE(0, 0);
    for (int c = 0; c < 4; c++) {
        if (c < 3) { GF_ISSUE((c+1)*32, (c+1)&1); CP_WAIT1(); } else { CP_WAIT0(); }
        __syncthreads();
        __half* As = AsB[c & 1];
        __half* Bs = BsB[c & 1];
        #pragma unroll
        for (int k16 = 0; k16 < 32; k16 += 16) {
            unsigned a[2][4];
            #pragma unroll
            for (int m2 = 0; m2 < 2; m2++) {
                int l = wm*32 + m2*16 + gid;
                a[m2][0] = *(const unsigned*)&As[l*40 + k16 + 2*tig];
                a[m2][1] = *(const unsigned*)&As[(l + 8)*40 + k16 + 2*tig];
                a[m2][2] = *(const unsigned*)&As[l*40 + k16 + 8 + 2*tig];
                a[m2][3] = *(const unsigned*)&As[(l + 8)*40 + k16 + 8 + 2*tig];
            }
            #pragma unroll
            for (int nt = 0; nt < 8; nt++) {
                int n = wn*64 + nt*8 + gid;
                unsigned b0 = *(const unsigned*)&Bs[n*40 + k16 + 2*tig];
                unsigned b1 = *(const unsigned*)&Bs[n*40 + k16 + 8 + 2*tig];
                #pragma unroll
                for (int m2 = 0; m2 < 2; m2++)
                    mma_f16(acc[m2][nt], a[m2], b0, b1);
            }
        }
        __syncthreads();
    }
    #pragma unroll
    for (int m2 = 0; m2 < 2; m2++) {
        #pragma unroll
        for (int nt = 0; nt < 8; nt++) {
            #pragma unroll
            for (int q = 0; q < 4; q++) {
                int row = wm*32 + m2*16 + gid + ((q >> 1) ? 8 : 0);
                int col = wn*64 + nt*8 + 2*tig + (q & 1);
                g_F[((size_t)h*JCOLS + j0 + row)*128 + col] = acc[m2][nt][q];
            }
        }
    }
}

// ---------------------------------------------------------------------------
__global__ void chunkscan_kernel(int layer) {
    int g = blockIdx.x*256 + threadIdx.x;
    int h = g >> 10;
    int r = g & 1023;
    int bb = r >> 6;
    int n = r & 63;
    int ib = (layer*HH + h)*NS + n;
    float wtr = g_wTr[ib], wti = g_wTi[ib];
    float sre = 0.f, sim = 0.f;
    size_t base = (size_t)h*JCOLS*128;
    #pragma unroll
    for (int c = 0; c < NCHUNK; c++) {
        size_t jo = base + (size_t)(c*16 + bb)*128;
        g_Sh[jo + n]      = __float2half(sre);
        g_Sh[jo + 64 + n] = __float2half(sim);
        float fre = g_F[jo + n];
        float fim = g_F[jo + 64 + n];
        float nr = fmaf(wtr, sre, fmaf(-wti, sim, fre));
        float ni = fmaf(wtr, sim, fmaf(wti, sre, fim));
        sre = nr; sim = ni;
    }
}

// ---------------------------------------------------------------------------
// GEMM-Y fp16 (cp.async 2-stage, 256 thr, warp 32mx64n):
//   y[j][t] = [U|S][j][k] @ ACT[t][k]^T   M=128 N=128 K=256
// ---------------------------------------------------------------------------
__global__ void __launch_bounds__(256) gemm_y_kernel(int layer, const float* __restrict__ Dski) {
    extern __shared__ __half smh[];
    __half* AsB[2] = { smh,            smh + 128*40 };
    __half* BsB[2] = { smh + 2*128*40, smh + 3*128*40 };
    int tid = threadIdx.x;
    int warp = tid >> 5, lane = tid & 31;
    int wm = warp & 3, wn = warp >> 2;
    int gid = lane >> 2, tig = lane & 3;
    int h = blockIdx.y;
    int j0 = blockIdx.x * 128;
    const __half* ACT = g_ACTh + (size_t)(layer*HH + h)*TCH*256;

    int ar[2], akq[2];
    size_t aub[2], asb[2];
    #pragma unroll
    for (int i = 0; i < 2; i++) {
        int idx = tid + i*256;
        ar[i] = idx >> 2; akq[i] = idx & 3;
        int jA = j0 + ar[i];
        aub[i] = ((size_t)((jA & 15)*HH + h))*LL + (jA >> 4)*TCH + akq[i]*8;
        asb[i] = ((size_t)h*JCOLS + jA)*128 + akq[i]*8;
    }

    float acc[2][8][4];
    #pragma unroll
    for (int i = 0; i < 2; i++)
        #pragma unroll
        for (int j = 0; j < 8; j++)
            #pragma unroll
            for (int q = 0; q < 4; q++) acc[i][j][q] = 0.f;

#define GY_ISSUE(k0, buf) { \
    _Pragma("unroll") \
    for (int i = 0; i < 2; i++) { \
        const __half* src = ((k0) < TCH) ? &g_ucmh[aub[i] + (k0)] : &g_Sh[asb[i] + (k0) - TCH]; \
        cp_async16_h(&AsB[buf][ar[i]*40 + akq[i]*8], src); \
        cp_async16_h(&BsB[buf][ar[i]*40 + akq[i]*8], &ACT[(size_t)ar[i]*256 + (k0) + akq[i]*8]); } \
    CP_COMMIT(); }

    GY_ISSUE(0, 0);
    for (int c = 0; c < 8; c++) {
        if (c < 7) { GY_ISSUE((c+1)*32, (c+1)&1); CP_WAIT1(); } else { CP_WAIT0(); }
        __syncthreads();
        __half* As = AsB[c & 1];
        __half* Bs = BsB[c & 1];
        #pragma unroll
        for (int k16 = 0; k16 < 32; k16 += 16) {
            unsigned a[2][4];
            #pragma unroll
            for (int m2 = 0; m2 < 2; m2++) {
                int l = wm*32 + m2*16 + gid;
                a[m2][0] = *(const unsigned*)&As[l*40 + k16 + 2*tig];
                a[m2][1] = *(const unsigned*)&As[(l + 8)*40 + k16 + 2*tig];
                a[m2][2] = *(const unsigned*)&As[l*40 + k16 + 8 + 2*tig];
                a[m2][3] = *(const unsigned*)&As[(l + 8)*40 + k16 + 8 + 2*tig];
            }
            #pragma unroll
            for (int nt = 0; nt < 8; nt++) {
                int n = wn*64 + nt*8 + gid;
                unsigned b0 = *(const unsigned*)&Bs[n*40 + k16 + 2*tig];
                unsigned b1 = *(const unsigned*)&Bs[n*40 + k16 + 8 + 2*tig];
                #pragma unroll
                for (int m2 = 0; m2 < 2; m2++)
                    mma_f16(acc[m2][nt], a[m2], b0, b1);
            }
        }
        __syncthreads();
    }
    float D = Dski[h];
    #pragma unroll
    for (int m2 = 0; m2 < 2; m2++) {
        #pragma unroll
        for (int nt = 0; nt < 8; nt++) {
            #pragma unroll
            for (int q = 0; q < 4; q++) {
                int row = wm*32 + m2*16 + gid + ((q >> 1) ? 8 : 0);
                int j = j0 + row;
                int t = wn*64 + nt*8 + 2*tig + (q & 1);
                int c = j >> 4, bb = j & 15;
                size_t base = ((size_t)(bb*HH + h))*LL + c*TCH;
                float u = __half2float(g_ucmh[base + t]);
                float yv = fmaf(D, u, acc[m2][nt][q]);
                g_ycm[base + t] = round_tf32(gelu_f(yv));
            }
        }
    }
}

// ---------------------------------------------------------------------------
// GLU fp16 (unchanged from R14).
// ---------------------------------------------------------------------------
__global__ void __launch_bounds__(256) glu_f16_kernel(int layer, const float* __restrict__ bias) {
    __shared__ __half As_h[128*44];
    __shared__ __half Bs1_h[64*40];
    __shared__ __half Bs2_h[64*40];
    int tid = threadIdx.x;
    int warp = tid >> 5, lane = tid & 31;
    int wm = warp & 3, wn = warp >> 2;
    int gid = lane >> 2, tig = lane & 3;
    int g0 = blockIdx.x * 64;
    int mt = blockIdx.y;
    int b  = mt >> 4;
    int l0 = (mt & 15) * 128;
    const __half* Wh = g_Wh + (size_t)layer * G2 * HH;

    float acc1[2][4][4], acc2[2][4][4];
    #pragma unroll
    for (int i = 0; i < 2; i++)
        #pragma unroll
        for (int j = 0; j < 4; j++)
            #pragma unroll
            for (int q = 0; q < 4; q++) { acc1[i][j][q] = 0.f; acc2[i][j][q] = 0.f; }

    for (int c = 0; c < 8; c++) {
        int k0 = c * 32;
        #pragma unroll
        for (int it = 0; it < 4; it++) {
            int e = tid + it*256;
            int l = e & 127, kk0 = (e >> 7) * 4;
            size_t gb = ((size_t)(b*HH + k0 + kk0))*LL + l0 + l;
            float v0 = g_ycm[gb];
            float v1 = g_ycm[gb + LL];
            float v2 = g_ycm[gb + 2*LL];
            float v3 = g_ycm[gb + 3*LL];
            uint2 pk = make_uint2(pack_h2(v0, v1), pack_h2(v2, v3));
            *(uint2*)&As_h[l*44 + kk0] = pk;
        }
        #pragma unroll
        for (int it = 0; it < 2; it++) {
            int e = tid + it*256;
            int mat = e >> 8, r = e & 255;
            int gg = r >> 2, kq = r & 3;
            const __half* src = &Wh[(size_t)((mat ? (256 + g0) : g0) + gg)*HH + k0 + kq*8];
            __half* dst = (mat ? Bs2_h : Bs1_h) + gg*40 + kq*8;
            cp_async16_h(dst, src);
        }
        CP_COMMIT();
        CP_WAIT0();
        __syncthreads();

        #pragma unroll
        for (int k16 = 0; k16 < 32; k16 += 16) {
            unsigned a[2][4];
            #pragma unroll
            for (int m2 = 0; m2 < 2; m2++) {
                int l = wm*32 + m2*16 + gid;
                a[m2][0] = *(const unsigned*)&As_h[l*44 + k16 + 2*tig];
                a[m2][1] = *(const unsigned*)&As_h[(l + 8)*44 + k16 + 2*tig];
                a[m2][2] = *(const unsigned*)&As_h[l*44 + k16 + 8 + 2*tig];
                a[m2][3] = *(const unsigned*)&As_h[(l + 8)*44 + k16 + 8 + 2*tig];
            }
            #pragma unroll
            for (int nt = 0; nt < 4; nt++) {
                int n = wn*32 + nt*8 + gid;
                unsigned b10 = *(const unsigned*)&Bs1_h[n*40 + k16 + 2*tig];
                unsigned b11 = *(const unsigned*)&Bs1_h[n*40 + k16 + 8 + 2*tig];
                unsigned b20 = *(const unsigned*)&Bs2_h[n*40 + k16 + 2*tig];
                unsigned b21 = *(const unsigned*)&Bs2_h[n*40 + k16 + 8 + 2*tig];
                #pragma unroll
                for (int m2 = 0; m2 < 2; m2++) {
                    mma_f16(acc1[m2][nt], a[m2], b10, b11);
                    mma_f16(acc2[m2][nt], a[m2], b20, b21);
                }
            }
        }
        __syncthreads();
    }
    #pragma unroll
    for (int m2 = 0; m2 < 2; m2++) {
        #pragma unroll
        for (int nt = 0; nt < 4; nt++) {
            #pragma unroll
            for (int q = 0; q < 4; q++) {
                int row = l0 + wm*32 + m2*16 + gid + ((q >> 1) ? 8 : 0);
                int col = g0 + wn*32 + nt*8 + 2*tig + (q & 1);
                float z1 = acc1[m2][nt][q] + bias[col];
                float z2 = acc2[m2][nt][q] + bias[col + 256];
                float sig = 1.0f/(1.0f + expf(-z2));
                g_hT[((size_t)(b*LL + row))*HH + col] += z1*sig;
            }
        }
    }
}

// ---------------------------------------------------------------------------
// Decoder fp16: (B*L,256)@(256,512)+b -> out.  Tile 128(m) x 64(r).
// A packed from g_hT fp32; B = g_Wdh [r][k] fp16 via cp.async.
// ---------------------------------------------------------------------------
__global__ void __launch_bounds__(256) dec_f16_kernel(const float* __restrict__ bias,
                                                      float* __restrict__ out) {
    __shared__ __half As_h[128*40];
    __shared__ __half Bs_h[64*40];
    int tid = threadIdx.x;
    int warp = tid >> 5, lane = tid & 31;
    int wm = warp & 3, wn = warp >> 2;
    int gid = lane >> 2, tig = lane & 3;
    int r0 = blockIdx.x * 64;
    int m0 = blockIdx.y * 128;

    float acc[2][4][4];
    #pragma unroll
    for (int i = 0; i < 2; i++)
        #pragma unroll
        for (int j = 0; j < 4; j++)
            #pragma unroll
            for (int q = 0; q < 4; q++) acc[i][j][q] = 0.f;

    for (int c = 0; c < 8; c++) {
        int k0 = c * 32;
        // B: 64 r-rows x 32 k halves via cp.async (256 ops, 1/thread)
        {
            int r = tid >> 2, kq = tid & 3;
            cp_async16_h(&Bs_h[r*40 + kq*8], &g_Wdh[(size_t)(r0 + r)*HH + k0 + kq*8]);
        }
        CP_COMMIT();
        // A: 128 rows x 32 k, packed from fp32 (1024 items, 4/thread)
        #pragma unroll
        for (int it = 0; it < 4; it++) {
            int e = tid + it*256;
            int l = e >> 3, kq4 = e & 7;
            float4 v = *(const float4*)&g_hT[((size_t)(m0 + l))*HH + k0 + kq4*4];
            uint2 pk = make_uint2(pack_h2(v.x, v.y), pack_h2(v.z, v.w));
            *(uint2*)&As_h[l*40 + kq4*4] = pk;
        }
        CP_WAIT0();
        __syncthreads();

        #pragma unroll
        for (int k16 = 0; k16 < 32; k16 += 16) {
            unsigned a[2][4];
            #pragma unroll
            for (int m2 = 0; m2 < 2; m2++) {
                int l = wm*32 + m2*16 + gid;
                a[m2][0] = *(const unsigned*)&As_h[l*40 + k16 + 2*tig];
                a[m2][1] = *(const unsigned*)&As_h[(l + 8)*40 + k16 + 2*tig];
                a[m2][2] = *(const unsigned*)&As_h[l*40 + k16 + 8 + 2*tig];
                a[m2][3] = *(const unsigned*)&As_h[(l + 8)*40 + k16 + 8 + 2*tig];
            }
            #pragma unroll
            for (int nt = 0; nt < 4; nt++) {
                int n = wn*32 + nt*8 + gid;
                unsigned b0 = *(const unsigned*)&Bs_h[n*40 + k16 + 2*tig];
                unsigned b1 = *(const unsigned*)&Bs_h[n*40 + k16 + 8 + 2*tig];
                #pragma unroll
                for (int m2 = 0; m2 < 2; m2++)
                    mma_f16(acc[m2][nt], a[m2], b0, b1);
            }
        }
        __syncthreads();
    }
    #pragma unroll
    for (int m2 = 0; m2 < 2; m2++) {
        #pragma unroll
        for (int nt = 0; nt < 4; nt++) {
            #pragma unroll
            for (int q = 0; q < 4; q++) {
                int row = m0 + wm*32 + m2*16 + gid + ((q >> 1) ? 8 : 0);
                int col = r0 + wn*32 + nt*8 + 2*tig + (q & 1);
                out[(size_t)row*REPR + col] = acc[m2][nt][q] + bias[col];
            }
        }
    }
}

// ---------------------------------------------------------------------------
extern "C" void kernel_launch(void* const* d_in, const int* in_sizes, int n_in,
                              void* d_out, int out_size) {
    const float* x        = (const float*)d_in[0];
    const float* embed_W  = (const float*)d_in[1];
    const float* embed_b  = (const float*)d_in[2];
    const float* log_dt   = (const float*)d_in[3];
    const float* A_log_re = (const float*)d_in[4];
    const float* A_im     = (const float*)d_in[5];
    const float* C_re     = (const float*)d_in[6];
    const float* C_im     = (const float*)d_in[7];
    const float* D_skip   = (const float*)d_in[8];
    const float* out_W    = (const float*)d_in[9];
    const float* out_b    = (const float*)d_in[10];
    const float* ln_g     = (const float*)d_in[11];
    const float* ln_b     = (const float*)d_in[12];
    const float* dec_W    = (const float*)d_in[13];
    const float* dec_b    = (const float*)d_in[14];
    float* out = (float*)d_out;

    const int PRE2_SMEM = (2*129*68 + 128) * sizeof(float);
    const int EMB_SMEM = (128*84 + EK*72) * sizeof(float);        // 66048
    const int GFY_SMEM = 4*128*40*sizeof(__half);                 // 40960
    static int smem_set = 0;
    if (!smem_set) {
        cudaFuncSetAttribute(embed_tc_kernel, cudaFuncAttributeMaxDynamicSharedMemorySize, EMB_SMEM);
        cudaFuncSetAttribute(precompute2_kernel, cudaFuncAttributeMaxDynamicSharedMemorySize,
                             PRE2_SMEM);
        cudaFuncSetAttribute(gemm_f_kernel, cudaFuncAttributeMaxDynamicSharedMemorySize, GFY_SMEM);
        cudaFuncSetAttribute(gemm_y_kernel, cudaFuncAttributeMaxDynamicSharedMemorySize, GFY_SMEM);
        smem_set = 1;
    }

    precompute_kernel<<<(NLAYER*HH*NS + 255)/256, 256>>>(log_dt, A_log_re, A_im, C_re, C_im);
    precompute2_kernel<<<NLAYER*HH, 128, PRE2_SMEM>>>();
    roundW_kernel<<<NLAYER*G2*HH/256, 256>>>(out_W);
    decWT_kernel<<<REPR, HH>>>(dec_W);
    embed_tc_kernel<<<dim3(4, BB*LL/128), 256, EMB_SMEM>>>(x, embed_W, embed_b);
    for (int i = 0; i < NLAYER; i++) {
        ln_kernel<<<BB*LL/32, 256>>>(ln_g + i*HH, ln_b + i*HH);
        gemm_f_kernel<<<dim3(2, HH), 256, GFY_SMEM>>>(i);
        chunkscan_kernel<<<HH*BB*NS/256, 256>>>(i);
        gemm_y_kernel<<<dim3(2, HH), 256, GFY_SMEM>>>(i, D_skip + i*HH);
        glu_f16_kernel<<<dim3(4, BB*LL/128), 256>>>(i, out_b + i*G2);
    }
    dec_f16_kernel<<<dim3(REPR/64, BB*LL/128), 256>>>(dec_b, out);
}